// round 3
// baseline (speedup 1.0000x reference)
#include <cuda_runtime.h>
#include <cuda_bf16.h>
#include <math.h>

// Problem constants
#define NN 65536
#define CIN 8
#define COUT 128
#define HH 256
#define OUTD 256
#define TT 5
#define G3 768            // 3*H
#define AUGK 384          // COUT + H
#define DECK 1280         // T*H

// ---------------------------------------------------------------------------
// Scratch (static device allocations — allowed; no cudaMalloc anywhere)
// ---------------------------------------------------------------------------
__device__ float g_xact[(size_t)TT * NN * COUT];    // conv out, then BN+ReLU in place  [t*N+n][128]
__device__ float g_gi[(size_t)TT * NN * G3];        // gi for GRU1, then reused for GRU2 [t*N+n][768]
__device__ float g_gh[(size_t)NN * G3];             // per-step hidden GEMM out          [n][768]
__device__ float g_hs[(size_t)TT * NN * HH];        // GRU1 hidden states                [t*N+n][256]
__device__ float g_feats[(size_t)NN * DECK];        // GRU2 outputs, decoder layout      [n][t*256+c]
__device__ float g_part[2 * 2048 * COUT];           // BN partial sums / sumsq per conv block
__device__ float g_bnscale[COUT];
__device__ float g_bnshift[COUT];

// ---------------------------------------------------------------------------
// Conv1d(k=3, pad=1, no bias) + BN partial stats.
// Block = 128 threads (one per out channel), 32 tracks per block.
// ---------------------------------------------------------------------------
__global__ __launch_bounds__(128) void conv_kernel(
    const float* __restrict__ tracks, const float* __restrict__ conv_w)
{
    __shared__ float s_in[32 * CIN * TT];   // 32 x 40
    const int c  = threadIdx.x;
    const int n0 = blockIdx.x * 32;

    float w[CIN * 3];
    #pragma unroll
    for (int j = 0; j < CIN * 3; j++) w[j] = conv_w[c * (CIN * 3) + j];

    for (int idx = c; idx < 32 * CIN * TT; idx += 128)
        s_in[idx] = tracks[(size_t)n0 * (CIN * TT) + idx];
    __syncthreads();

    float sum = 0.f, sq = 0.f;
    for (int nl = 0; nl < 32; nl++) {
        const float* in = &s_in[nl * CIN * TT];
        #pragma unroll
        for (int t = 0; t < TT; t++) {
            float a = 0.f;
            #pragma unroll
            for (int ci = 0; ci < CIN; ci++) {
                #pragma unroll
                for (int k = 0; k < 3; k++) {
                    const int tt = t + k - 1;
                    if (tt >= 0 && tt < TT)
                        a += in[ci * TT + tt] * w[ci * 3 + k];
                }
            }
            g_xact[((size_t)t * NN + n0 + nl) * COUT + c] = a;
            sum += a; sq += a * a;
        }
    }
    g_part[blockIdx.x * COUT + c] = sum;
    g_part[2048 * COUT + blockIdx.x * COUT + c] = sq;
}

// Deterministic BN finalize: 1 block, 128 threads, serial double-precision sum.
__global__ void bn_finalize_kernel(const float* __restrict__ gamma,
                                   const float* __restrict__ beta)
{
    const int c = threadIdx.x;
    double s = 0.0, q = 0.0;
    for (int b = 0; b < 2048; b++) {
        s += (double)g_part[b * COUT + c];
        q += (double)g_part[2048 * COUT + b * COUT + c];
    }
    const double inv = 1.0 / ((double)TT * (double)NN);
    const double mean = s * inv;
    const double var  = q * inv - mean * mean;
    const float sc = gamma[c] * rsqrtf((float)var + 1e-5f);
    g_bnscale[c] = sc;
    g_bnshift[c] = beta[c] - (float)mean * sc;
}

__global__ void bn_relu_kernel()
{
    const size_t i = (size_t)blockIdx.x * blockDim.x + threadIdx.x;
    const int c = (int)(i & (COUT - 1));
    const float v = g_xact[i] * g_bnscale[c] + g_bnshift[c];
    g_xact[i] = v > 0.f ? v : 0.f;
}

// ---------------------------------------------------------------------------
// GEMM:  C[m][n] (+)= sum_k A[m][k] * B[n][k]     (A row-major lda, B row-major ldb)
// Tiles: 128x64x16, 256 threads, 8x4 per-thread micro-tile.
// All M % 128 == 0, N % 64 == 0, K % 16 == 0 in this problem -> no bounds checks.
// ---------------------------------------------------------------------------
#define BM 128
#define BN 64
#define BK 16

template<bool ACCUM>
__global__ __launch_bounds__(256) void gemm_tn(
    const float* __restrict__ A, int lda,
    const float* __restrict__ B, int ldb,
    float* __restrict__ C, int ldc, int K)
{
    __shared__ __align__(16) float As[BK][BM];
    __shared__ __align__(16) float Bs[BK][BN];

    const int tid = threadIdx.x;
    const int tx = tid & 15;   // col group (0..15) -> 4 cols
    const int ty = tid >> 4;   // row group (0..15) -> 8 rows
    const long m0 = (long)blockIdx.y * BM;
    const int  n0 = blockIdx.x * BN;

    float acc[8][4];
    #pragma unroll
    for (int i = 0; i < 8; i++)
        #pragma unroll
        for (int j = 0; j < 4; j++) acc[i][j] = 0.f;

    for (int k0 = 0; k0 < K; k0 += BK) {
        // Load A tile: 512 float4s (row = f>>2, kk = (f&3)*4), transposed into smem
        #pragma unroll
        for (int u = 0; u < 2; u++) {
            const int f = tid + u * 256;
            const int row = f >> 2;
            const int kk = (f & 3) * 4;
            const float4 v = *reinterpret_cast<const float4*>(
                A + (m0 + row) * (long)lda + k0 + kk);
            As[kk + 0][row] = v.x; As[kk + 1][row] = v.y;
            As[kk + 2][row] = v.z; As[kk + 3][row] = v.w;
        }
        // Load B tile: 256 float4s
        {
            const int row = tid >> 2;
            const int kk = (tid & 3) * 4;
            const float4 v = *reinterpret_cast<const float4*>(
                B + (long)(n0 + row) * ldb + k0 + kk);
            Bs[kk + 0][row] = v.x; Bs[kk + 1][row] = v.y;
            Bs[kk + 2][row] = v.z; Bs[kk + 3][row] = v.w;
        }
        __syncthreads();

        #pragma unroll
        for (int bk = 0; bk < BK; bk++) {
            const float4 a0 = *reinterpret_cast<const float4*>(&As[bk][ty * 8]);
            const float4 a1 = *reinterpret_cast<const float4*>(&As[bk][ty * 8 + 4]);
            const float4 b  = *reinterpret_cast<const float4*>(&Bs[bk][tx * 4]);
            const float av[8] = {a0.x, a0.y, a0.z, a0.w, a1.x, a1.y, a1.z, a1.w};
            const float bv[4] = {b.x, b.y, b.z, b.w};
            #pragma unroll
            for (int i = 0; i < 8; i++)
                #pragma unroll
                for (int j = 0; j < 4; j++)
                    acc[i][j] += av[i] * bv[j];
        }
        __syncthreads();
    }

    #pragma unroll
    for (int i = 0; i < 8; i++) {
        const long m = m0 + ty * 8 + i;
        float* crow = C + m * (long)ldc + n0 + tx * 4;
        if (ACCUM) {
            float4 c0 = *reinterpret_cast<float4*>(crow);
            c0.x += acc[i][0]; c0.y += acc[i][1];
            c0.z += acc[i][2]; c0.w += acc[i][3];
            *reinterpret_cast<float4*>(crow) = c0;
        } else {
            *reinterpret_cast<float4*>(crow) =
                make_float4(acc[i][0], acc[i][1], acc[i][2], acc[i][3]);
        }
    }
}

// ---------------------------------------------------------------------------
// GRU gate elementwise. Block = one sample n, 256 threads = hidden units.
// FIRST: h_prev = 0 and gh = b_hh only (skips the GEMM for the first step).
// ---------------------------------------------------------------------------
template<bool FIRST>
__global__ __launch_bounds__(256) void gru_gates(
    const float* __restrict__ gi,     // [N][768]
    const float* __restrict__ gh,     // [N][768] (ignored if FIRST)
    const float* __restrict__ hprev,  // stride hs (ignored if FIRST)
    float* __restrict__ hout,         // stride hs
    long hs,
    const float* __restrict__ bih, const float* __restrict__ bhh)
{
    const long n = blockIdx.x;
    const int c = threadIdx.x;
    const float* girow = gi + n * G3;
    const float ir  = girow[c]       + bih[c];
    const float iz  = girow[c + 256] + bih[c + 256];
    const float inn = girow[c + 512] + bih[c + 512];
    float hr, hz, hn, h;
    if (FIRST) {
        hr = bhh[c]; hz = bhh[c + 256]; hn = bhh[c + 512]; h = 0.f;
    } else {
        const float* ghrow = gh + n * G3;
        hr = ghrow[c]       + bhh[c];
        hz = ghrow[c + 256] + bhh[c + 256];
        hn = ghrow[c + 512] + bhh[c + 512];
        h = hprev[n * hs + c];
    }
    const float r = 1.f / (1.f + expf(-(ir + hr)));
    const float z = 1.f / (1.f + expf(-(iz + hz)));
    const float nn = tanhf(inn + r * hn);
    hout[n * hs + c] = (1.f - z) * nn + z * h;
}

// ---------------------------------------------------------------------------
// bias + LayerNorm + leaky ReLU, in place on d_out. Block = one row.
// ---------------------------------------------------------------------------
__global__ __launch_bounds__(256) void ln_leaky_kernel(
    float* __restrict__ y, const float* __restrict__ dec_b,
    const float* __restrict__ ln_w, const float* __restrict__ ln_b)
{
    __shared__ float red[256];
    const long r = blockIdx.x;
    const int c = threadIdx.x;
    const float v = y[r * OUTD + c] + dec_b[c];

    red[c] = v;
    __syncthreads();
    #pragma unroll
    for (int s = 128; s > 0; s >>= 1) {
        if (c < s) red[c] += red[c + s];
        __syncthreads();
    }
    const float mean = red[0] * (1.f / OUTD);
    __syncthreads();

    const float d = v - mean;
    red[c] = d * d;
    __syncthreads();
    #pragma unroll
    for (int s = 128; s > 0; s >>= 1) {
        if (c < s) red[c] += red[c + s];
        __syncthreads();
    }
    const float var = red[0] * (1.f / OUTD);

    const float o = d * rsqrtf(var + 1e-5f) * ln_w[c] + ln_b[c];
    y[r * OUTD + c] = o >= 0.f ? o : 0.05f * o;
}

// ---------------------------------------------------------------------------
// Launch
// ---------------------------------------------------------------------------
extern "C" void kernel_launch(void* const* d_in, const int* in_sizes, int n_in,
                              void* d_out, int out_size)
{
    const float* tracks   = (const float*)d_in[0];
    const float* conv_w   = (const float*)d_in[1];
    const float* bn_gamma = (const float*)d_in[2];
    const float* bn_beta  = (const float*)d_in[3];
    const float* g1_wih   = (const float*)d_in[4];
    const float* g1_whh   = (const float*)d_in[5];
    const float* g1_bih   = (const float*)d_in[6];
    const float* g1_bhh   = (const float*)d_in[7];
    const float* g2_wih   = (const float*)d_in[8];
    const float* g2_whh   = (const float*)d_in[9];
    const float* g2_bih   = (const float*)d_in[10];
    const float* g2_bhh   = (const float*)d_in[11];
    const float* dec_w    = (const float*)d_in[12];
    const float* dec_b    = (const float*)d_in[13];
    const float* ln_w     = (const float*)d_in[14];
    const float* ln_b     = (const float*)d_in[15];
    float* out = (float*)d_out;

    float *xact, *gi, *gh, *hs, *feats;
    cudaGetSymbolAddress((void**)&xact,  g_xact);
    cudaGetSymbolAddress((void**)&gi,    g_gi);
    cudaGetSymbolAddress((void**)&gh,    g_gh);
    cudaGetSymbolAddress((void**)&hs,    g_hs);
    cudaGetSymbolAddress((void**)&feats, g_feats);

    // 1. Conv + BN stats + BN apply + ReLU
    conv_kernel<<<NN / 32, 128>>>(tracks, conv_w);
    bn_finalize_kernel<<<1, 128>>>(bn_gamma, bn_beta);
    bn_relu_kernel<<<(TT * NN * COUT) / 256, 256>>>();

    // 2. gi1 = x @ g1_wih^T   [T*N, 768] (K=128)
    gemm_tn<false><<<dim3(G3 / BN, (TT * NN) / BM), 256>>>(
        xact, COUT, g1_wih, COUT, gi, G3, COUT);

    // 3. GRU1, backward over t (t=T-1 uses h=0 -> no GEMM)
    gru_gates<true><<<NN, 256>>>(
        gi + (size_t)(TT - 1) * NN * G3, nullptr, nullptr,
        hs + (size_t)(TT - 1) * NN * HH, HH, g1_bih, g1_bhh);
    for (int t = TT - 2; t >= 0; t--) {
        gemm_tn<false><<<dim3(G3 / BN, NN / BM), 256>>>(
            hs + (size_t)(t + 1) * NN * HH, HH, g1_whh, HH, gh, G3, HH);
        gru_gates<false><<<NN, 256>>>(
            gi + (size_t)t * NN * G3, gh,
            hs + (size_t)(t + 1) * NN * HH,
            hs + (size_t)t * NN * HH, HH, g1_bih, g1_bhh);
    }

    // 4. gi2 = x @ W2[:, :128]^T + Hs @ W2[:, 128:384]^T  (reuse g_gi)
    gemm_tn<false><<<dim3(G3 / BN, (TT * NN) / BM), 256>>>(
        xact, COUT, g2_wih, AUGK, gi, G3, COUT);
    gemm_tn<true><<<dim3(G3 / BN, (TT * NN) / BM), 256>>>(
        hs, HH, g2_wih + COUT, AUGK, gi, G3, HH);

    // 5. GRU2, forward over t; h_t written straight into decoder layout
    //    feats[n][t*256 + c]  (stride 1280)
    gru_gates<true><<<NN, 256>>>(
        gi, nullptr, nullptr, feats, DECK, g2_bih, g2_bhh);
    for (int t = 1; t < TT; t++) {
        gemm_tn<false><<<dim3(G3 / BN, NN / BM), 256>>>(
            feats + (size_t)(t - 1) * HH, DECK, g2_whh, HH, gh, G3, HH);
        gru_gates<false><<<NN, 256>>>(
            gi + (size_t)t * NN * G3, gh,
            feats + (size_t)(t - 1) * HH,
            feats + (size_t)t * HH, DECK, g2_bih, g2_bhh);
    }

    // 6. Decoder GEMM straight into d_out, then fused bias+LN+leaky in place
    gemm_tn<false><<<dim3(OUTD / BN, NN / BM), 256>>>(
        feats, DECK, dec_w, DECK, out, OUTD, DECK);
    ln_leaky_kernel<<<NN, 256>>>(out, dec_b, ln_w, ln_b);
}

// round 7
// speedup vs baseline: 2.3589x; 2.3589x over previous
#include <cuda_runtime.h>
#include <cuda_bf16.h>
#include <math.h>
#include <stdint.h>

// ---------------------------------------------------------------------------
// Problem constants
// ---------------------------------------------------------------------------
#define NN 65536
#define CIN 8
#define COUT 128
#define HH 256
#define OUTD 256
#define TT 5
#define G3 768             // 3*H (gate dim)
#define K1 (3*COUT)        // 384   expanded K: x only
#define KH (3*HH)          // 768   expanded K: hidden
#define KA (3*(COUT+HH))   // 1152  expanded K: [x | h1]
#define KD (3*TT*HH)       // 3840  expanded K: decoder input

// ---------------------------------------------------------------------------
// Device scratch — total ~1.67 GB (must stay < 2 GiB or host link fails
// with GOTPCREL relocation overflow; learned R5)
// ---------------------------------------------------------------------------
__device__ __nv_bfloat16  g_aug3[(size_t)TT * NN * KA];     // 755 MB [t*N+n][1152] triplets: x | h1
__device__ __nv_bfloat16  g_feats3[(size_t)NN * KD];        // 503 MB [n][3840] GRU2 states, decoder layout
__device__ float          g_gi[(size_t)NN * G3];            // 201 MB per-step gi (also aliases conv out)
__device__ float          g_gh[(size_t)NN * G3];            // 201 MB per-step gh
__device__ float          g_part[2 * 2048 * COUT];
__device__ float          g_bnscale[COUT];
__device__ float          g_bnshift[COUT];
__device__ __nv_bfloat16  g_w1ih3[G3 * K1];
__device__ __nv_bfloat16  g_w1hh3[G3 * KH];
__device__ __nv_bfloat16  g_w2ih3[G3 * KA];
__device__ __nv_bfloat16  g_w2hh3[G3 * KH];
__device__ __nv_bfloat16  g_dec3[OUTD * KD];

// Conv fp32 output aliases g_gi: 5*65536*128 floats (41.9M) < 50.3M capacity.
// bn_relu_expand consumes it before the first GEMM overwrites g_gi.

// ---------------------------------------------------------------------------
// Helpers (baseline PTX only: cp.async / ldmatrix / mma.sync — no tcgen05,
// which is sm_100a-only and the harness compiles for base sm_100)
// ---------------------------------------------------------------------------
__device__ __forceinline__ uint32_t smem_u32(const void* p) {
    uint32_t a;
    asm("{ .reg .u64 t; cvta.to.shared.u64 t, %1; cvt.u32.u64 %0, t; }"
        : "=r"(a) : "l"(p));
    return a;
}
#define SW128(x) ((x) ^ (((x) >> 3) & 0x70))

#define CP_ASYNC16(dst, src) \
    asm volatile("cp.async.cg.shared.global [%0], [%1], 16;" \
        :: "r"(dst), "l"(src) : "memory")
#define CP_COMMIT()  asm volatile("cp.async.commit_group;" ::: "memory")
#define CP_WAIT1()   asm volatile("cp.async.wait_group 1;" ::: "memory")

#define LDMATRIX_X4(r0, r1, r2, r3, addr) \
    asm volatile("ldmatrix.sync.aligned.m8n8.x4.shared.b16 {%0,%1,%2,%3}, [%4];" \
        : "=r"(r0), "=r"(r1), "=r"(r2), "=r"(r3) : "r"(addr))
// B smem is [n][k] with k contiguous == col-major KxN: NON-trans ldmatrix
// yields the b0/b1 fragment directly (R6 fix: .trans here was the bug).
#define LDMATRIX_X2(r0, r1, addr) \
    asm volatile("ldmatrix.sync.aligned.m8n8.x2.shared.b16 {%0,%1}, [%2];" \
        : "=r"(r0), "=r"(r1) : "r"(addr))

#define MMA_BF16(d, a, b) \
    asm volatile("mma.sync.aligned.m16n8k16.row.col.f32.bf16.bf16.f32 " \
        "{%0,%1,%2,%3}, {%4,%5,%6,%7}, {%8,%9}, {%0,%1,%2,%3};" \
        : "+f"((d)[0]), "+f"((d)[1]), "+f"((d)[2]), "+f"((d)[3]) \
        : "r"((a)[0]), "r"((a)[1]), "r"((a)[2]), "r"((a)[3]), \
          "r"((b)[0]), "r"((b)[1]))

// ---------------------------------------------------------------------------
// HMMA GEMM:  C[m][n] = sum_k A[m][k]*B[n][k]   (both K-major bf16, C fp32)
// CTA tile 128x128x64, 3-stage cp.async pipeline, SW128 swizzle + ldmatrix.
// Grid: (Ntotal/128, Mtotal/128). K = ktiles*64.
// ---------------------------------------------------------------------------
#define STAGE_BYTES 32768                // A 16KB + B 16KB
#define GEMM_SMEM   (3 * STAGE_BYTES + 1024)

__global__ void __launch_bounds__(256, 2) gemm3_kernel(
    const __nv_bfloat16* __restrict__ A, int lda,
    const __nv_bfloat16* __restrict__ B, int ldb,
    float* __restrict__ C, int ldc, int ktiles)
{
    extern __shared__ char smem_raw[];
    const uint32_t sb = (smem_u32(smem_raw) + 1023u) & ~1023u;

    const int tid  = threadIdx.x;
    const int wid  = tid >> 5;
    const int lane = tid & 31;
    const int wm = wid & 1;              // 2 M-warps  (64 rows each)
    const int wn = wid >> 1;             // 4 N-warps  (32 cols each)
    const size_t m0 = (size_t)blockIdx.y * 128;
    const int    n0 = blockIdx.x * 128;

    float acc[4][4][4];
    #pragma unroll
    for (int i = 0; i < 4; i++)
        #pragma unroll
        for (int j = 0; j < 4; j++)
            #pragma unroll
            for (int v = 0; v < 4; v++) acc[i][j][v] = 0.f;

    // ---- prologue: stages 0,1 ----
    #pragma unroll
    for (int s = 0; s < 2; s++) {
        const uint32_t sA = sb + s * STAGE_BYTES;
        const uint32_t sB = sA + 16384u;
        #pragma unroll
        for (int i = 0; i < 4; i++) {
            const int idx = tid + (i << 8);
            const int r = idx >> 3, c = idx & 7;
            const __nv_bfloat16* ga = A + (m0 + r) * (size_t)lda + (size_t)s * 64 + c * 8;
            const __nv_bfloat16* gb = B + (size_t)(n0 + r) * (size_t)ldb + (size_t)s * 64 + c * 8;
            CP_ASYNC16(sA + (uint32_t)SW128(r * 128 + c * 16), ga);
            CP_ASYNC16(sB + (uint32_t)SW128(r * 128 + c * 16), gb);
        }
        CP_COMMIT();
    }

    for (int kt = 0; kt < ktiles; kt++) {
        CP_WAIT1();
        __syncthreads();

        const uint32_t sA = sb + (uint32_t)(kt % 3) * STAGE_BYTES;
        const uint32_t sB = sA + 16384u;

        // ---- compute tile kt ----
        #pragma unroll
        for (int kc = 0; kc < 4; kc++) {
            uint32_t afr[4][4];
            uint32_t bfr[4][2];
            #pragma unroll
            for (int im = 0; im < 4; im++) {
                const int m  = wm * 64 + im * 16 + ((lane >> 3) & 1) * 8 + (lane & 7);
                const int kk = kc * 16 + (lane >> 4) * 8;
                const uint32_t addr = sA + (uint32_t)SW128(m * 128 + kk * 2);
                LDMATRIX_X4(afr[im][0], afr[im][1], afr[im][2], afr[im][3], addr);
            }
            #pragma unroll
            for (int in_ = 0; in_ < 4; in_++) {
                const int n  = wn * 32 + in_ * 8 + (lane & 7);
                const int kk = kc * 16 + ((lane >> 3) & 1) * 8;
                const uint32_t addr = sB + (uint32_t)SW128(n * 128 + kk * 2);
                LDMATRIX_X2(bfr[in_][0], bfr[in_][1], addr);
            }
            #pragma unroll
            for (int im = 0; im < 4; im++)
                #pragma unroll
                for (int in_ = 0; in_ < 4; in_++)
                    MMA_BF16(acc[im][in_], afr[im], bfr[in_]);
        }

        // ---- issue stage kt+2 ----
        if (kt + 2 < ktiles) {
            const int s = kt + 2;
            const uint32_t dA = sb + (uint32_t)(s % 3) * STAGE_BYTES;
            const uint32_t dB = dA + 16384u;
            #pragma unroll
            for (int i = 0; i < 4; i++) {
                const int idx = tid + (i << 8);
                const int r = idx >> 3, c = idx & 7;
                const __nv_bfloat16* ga = A + (m0 + r) * (size_t)lda + (size_t)s * 64 + c * 8;
                const __nv_bfloat16* gb = B + (size_t)(n0 + r) * (size_t)ldb + (size_t)s * 64 + c * 8;
                CP_ASYNC16(dA + (uint32_t)SW128(r * 128 + c * 16), ga);
                CP_ASYNC16(dB + (uint32_t)SW128(r * 128 + c * 16), gb);
            }
        }
        CP_COMMIT();
    }

    // ---- epilogue ----
    const int grp = lane >> 2;
    const int tig = lane & 3;
    #pragma unroll
    for (int im = 0; im < 4; im++) {
        const size_t row = m0 + wm * 64 + im * 16 + grp;
        #pragma unroll
        for (int in_ = 0; in_ < 4; in_++) {
            const int col = n0 + wn * 32 + in_ * 8 + 2 * tig;
            *reinterpret_cast<float2*>(C + row * (size_t)ldc + col) =
                make_float2(acc[im][in_][0], acc[im][in_][1]);
            *reinterpret_cast<float2*>(C + (row + 8) * (size_t)ldc + col) =
                make_float2(acc[im][in_][2], acc[im][in_][3]);
        }
    }
}

// ---------------------------------------------------------------------------
// Conv1d(k=3,pad=1) + BN partial stats (fp32). Output -> g_gi (aliased).
// ---------------------------------------------------------------------------
__global__ __launch_bounds__(128) void conv_kernel(
    const float* __restrict__ tracks, const float* __restrict__ conv_w)
{
    __shared__ float s_in[32 * CIN * TT];
    const int c  = threadIdx.x;
    const int n0 = blockIdx.x * 32;

    float w[CIN * 3];
    #pragma unroll
    for (int j = 0; j < CIN * 3; j++) w[j] = conv_w[c * (CIN * 3) + j];

    for (int idx = c; idx < 32 * CIN * TT; idx += 128)
        s_in[idx] = tracks[(size_t)n0 * (CIN * TT) + idx];
    __syncthreads();

    float sum = 0.f, sq = 0.f;
    for (int nl = 0; nl < 32; nl++) {
        const float* in = &s_in[nl * CIN * TT];
        #pragma unroll
        for (int t = 0; t < TT; t++) {
            float a = 0.f;
            #pragma unroll
            for (int ci = 0; ci < CIN; ci++) {
                #pragma unroll
                for (int k = 0; k < 3; k++) {
                    const int tt = t + k - 1;
                    if (tt >= 0 && tt < TT)
                        a += in[ci * TT + tt] * w[ci * 3 + k];
                }
            }
            g_gi[((size_t)t * NN + n0 + nl) * COUT + c] = a;
            sum += a; sq += a * a;
        }
    }
    g_part[blockIdx.x * COUT + c] = sum;
    g_part[2048 * COUT + blockIdx.x * COUT + c] = sq;
}

__global__ void bn_finalize_kernel(const float* __restrict__ gamma,
                                   const float* __restrict__ beta)
{
    const int c = threadIdx.x;
    double s = 0.0, q = 0.0;
    for (int b = 0; b < 2048; b++) {
        s += (double)g_part[b * COUT + c];
        q += (double)g_part[2048 * COUT + b * COUT + c];
    }
    const double inv = 1.0 / ((double)TT * (double)NN);
    const double mean = s * inv;
    const double var  = q * inv - mean * mean;
    const float sc = gamma[c] * rsqrtf((float)var + 1e-5f);
    g_bnscale[c] = sc;
    g_bnshift[c] = beta[c] - (float)mean * sc;
}

// BN + ReLU on conv out (in g_gi), expand to {hi, lo, hi} triplets into
// g_aug3 cols [0, 384). Must run before any GEMM writes g_gi.
__global__ __launch_bounds__(256) void bn_relu_expand_kernel()
{
    const size_t i = (size_t)blockIdx.x * 256 + threadIdx.x;
    const int c = (int)(i & (COUT - 1));
    const size_t m = i >> 7;
    float v = g_gi[i] * g_bnscale[c] + g_bnshift[c];
    v = v > 0.f ? v : 0.f;
    const __nv_bfloat16 hi = __float2bfloat16_rn(v);
    const __nv_bfloat16 lo = __float2bfloat16_rn(v - __bfloat162float(hi));
    __nv_bfloat16* o = g_aug3 + m * KA + 3 * c;
    o[0] = hi; o[1] = lo; o[2] = hi;
}

// Weight expand: fp32 -> {hi, hi, lo} triplets (flat; preserves row-major)
__global__ __launch_bounds__(256) void expand_weight_kernel(
    const float* __restrict__ w, __nv_bfloat16* __restrict__ out, int n)
{
    const int i = blockIdx.x * 256 + threadIdx.x;
    if (i >= n) return;
    const float v = w[i];
    const __nv_bfloat16 hi = __float2bfloat16_rn(v);
    const __nv_bfloat16 lo = __float2bfloat16_rn(v - __bfloat162float(hi));
    out[3 * i + 0] = hi; out[3 * i + 1] = hi; out[3 * i + 2] = lo;
}

// ---------------------------------------------------------------------------
// GRU gates. fp32 gi/gh; h_prev read from triplets (hi+lo); writes triplets.
// ---------------------------------------------------------------------------
template<bool FIRST>
__global__ __launch_bounds__(256) void gru_gates_kernel(
    const float* __restrict__ gi, const float* __restrict__ gh,
    const __nv_bfloat16* __restrict__ hprev, size_t hp_ld,
    __nv_bfloat16* __restrict__ hout, size_t ho_ld,
    const float* __restrict__ bih, const float* __restrict__ bhh)
{
    const size_t n = blockIdx.x;
    const int c = threadIdx.x;
    const float* gir = gi + n * G3;
    const float ir  = gir[c]       + bih[c];
    const float iz  = gir[c + 256] + bih[c + 256];
    const float in_ = gir[c + 512] + bih[c + 512];
    float hr, hz, hn, h;
    if (FIRST) {
        hr = bhh[c]; hz = bhh[c + 256]; hn = bhh[c + 512]; h = 0.f;
    } else {
        const float* ghr = gh + n * G3;
        hr = ghr[c]       + bhh[c];
        hz = ghr[c + 256] + bhh[c + 256];
        hn = ghr[c + 512] + bhh[c + 512];
        const __nv_bfloat16* hp = hprev + n * hp_ld + 3 * c;
        h = __bfloat162float(hp[0]) + __bfloat162float(hp[1]);
    }
    const float r = 1.f / (1.f + expf(-(ir + hr)));
    const float z = 1.f / (1.f + expf(-(iz + hz)));
    const float nn2 = tanhf(in_ + r * hn);
    const float ho = (1.f - z) * nn2 + z * h;
    const __nv_bfloat16 hi = __float2bfloat16_rn(ho);
    const __nv_bfloat16 lo = __float2bfloat16_rn(ho - __bfloat162float(hi));
    __nv_bfloat16* o = hout + n * ho_ld + 3 * c;
    o[0] = hi; o[1] = lo; o[2] = hi;
}

// ---------------------------------------------------------------------------
// bias + LayerNorm + leaky ReLU in place on d_out
// ---------------------------------------------------------------------------
__global__ __launch_bounds__(256) void ln_leaky_kernel(
    float* __restrict__ y, const float* __restrict__ dec_b,
    const float* __restrict__ ln_w, const float* __restrict__ ln_b)
{
    __shared__ float red[256];
    const size_t r = blockIdx.x;
    const int c = threadIdx.x;
    const float v = y[r * OUTD + c] + dec_b[c];

    red[c] = v;
    __syncthreads();
    #pragma unroll
    for (int s = 128; s > 0; s >>= 1) {
        if (c < s) red[c] += red[c + s];
        __syncthreads();
    }
    const float mean = red[0] * (1.f / OUTD);
    __syncthreads();

    const float d = v - mean;
    red[c] = d * d;
    __syncthreads();
    #pragma unroll
    for (int s = 128; s > 0; s >>= 1) {
        if (c < s) red[c] += red[c + s];
        __syncthreads();
    }
    const float var = red[0] * (1.f / OUTD);

    const float o = d * rsqrtf(var + 1e-5f) * ln_w[c] + ln_b[c];
    y[r * OUTD + c] = o >= 0.f ? o : 0.05f * o;
}

// ---------------------------------------------------------------------------
// Launch
// ---------------------------------------------------------------------------
extern "C" void kernel_launch(void* const* d_in, const int* in_sizes, int n_in,
                              void* d_out, int out_size)
{
    const float* tracks   = (const float*)d_in[0];
    const float* conv_w   = (const float*)d_in[1];
    const float* bn_gamma = (const float*)d_in[2];
    const float* bn_beta  = (const float*)d_in[3];
    const float* g1_wih   = (const float*)d_in[4];
    const float* g1_whh   = (const float*)d_in[5];
    const float* g1_bih   = (const float*)d_in[6];
    const float* g1_bhh   = (const float*)d_in[7];
    const float* g2_wih   = (const float*)d_in[8];
    const float* g2_whh   = (const float*)d_in[9];
    const float* g2_bih   = (const float*)d_in[10];
    const float* g2_bhh   = (const float*)d_in[11];
    const float* dec_w    = (const float*)d_in[12];
    const float* dec_b    = (const float*)d_in[13];
    const float* ln_w     = (const float*)d_in[14];
    const float* ln_b     = (const float*)d_in[15];
    float* out = (float*)d_out;

    __nv_bfloat16 *aug3, *feats3, *w1ih3, *w1hh3, *w2ih3, *w2hh3, *dec3;
    float *gi, *gh;
    cudaGetSymbolAddress((void**)&aug3,   g_aug3);
    cudaGetSymbolAddress((void**)&feats3, g_feats3);
    cudaGetSymbolAddress((void**)&gi,     g_gi);
    cudaGetSymbolAddress((void**)&gh,     g_gh);
    cudaGetSymbolAddress((void**)&w1ih3,  g_w1ih3);
    cudaGetSymbolAddress((void**)&w1hh3,  g_w1hh3);
    cudaGetSymbolAddress((void**)&w2ih3,  g_w2ih3);
    cudaGetSymbolAddress((void**)&w2hh3,  g_w2hh3);
    cudaGetSymbolAddress((void**)&dec3,   g_dec3);

    cudaFuncSetAttribute(gemm3_kernel,
                         cudaFuncAttributeMaxDynamicSharedMemorySize, GEMM_SMEM);

    // 0. Expand weights to bf16 triplets
    expand_weight_kernel<<<(G3 * COUT + 255) / 256, 256>>>(g1_wih, w1ih3, G3 * COUT);
    expand_weight_kernel<<<(G3 * HH + 255) / 256, 256>>>(g1_whh, w1hh3, G3 * HH);
    expand_weight_kernel<<<(G3 * (COUT + HH) + 255) / 256, 256>>>(g2_wih, w2ih3, G3 * (COUT + HH));
    expand_weight_kernel<<<(G3 * HH + 255) / 256, 256>>>(g2_whh, w2hh3, G3 * HH);
    expand_weight_kernel<<<(OUTD * TT * HH + 255) / 256, 256>>>(dec_w, dec3, OUTD * TT * HH);

    // 1. Conv (out -> g_gi alias) + BN stats + BN/ReLU/expand into aug3[:, 0:384)
    conv_kernel<<<NN / 32, 128>>>(tracks, conv_w);
    bn_finalize_kernel<<<1, 128>>>(bn_gamma, bn_beta);
    bn_relu_expand_kernel<<<((size_t)TT * NN * COUT) / 256, 256>>>();

    const dim3 ggrid(G3 / 128, NN / 128);   // per-step GEMM grid (3072 CTAs)

    // 2+3. GRU1 backward over t (per-step gi GEMM; first step has no gh GEMM)
    for (int t = TT - 1; t >= 0; t--) {
        gemm3_kernel<<<ggrid, 256, GEMM_SMEM>>>(
            aug3 + (size_t)t * NN * KA, KA, w1ih3, K1, gi, G3, K1 / 64);
        if (t == TT - 1) {
            gru_gates_kernel<true><<<NN, 256>>>(
                gi, nullptr, nullptr, 0,
                aug3 + (size_t)t * NN * KA + K1, KA, g1_bih, g1_bhh);
        } else {
            gemm3_kernel<<<ggrid, 256, GEMM_SMEM>>>(
                aug3 + (size_t)(t + 1) * NN * KA + K1, KA, w1hh3, KH, gh, G3, KH / 64);
            gru_gates_kernel<false><<<NN, 256>>>(
                gi, gh,
                aug3 + (size_t)(t + 1) * NN * KA + K1, KA,
                aug3 + (size_t)t * NN * KA + K1, KA, g1_bih, g1_bhh);
        }
    }

    // 4+5. GRU2 forward over t (per-step gi2 GEMM, K=1152); hidden written
    //      straight into decoder layout feats3[n][t*768 .. t*768+768)
    for (int t = 0; t < TT; t++) {
        gemm3_kernel<<<ggrid, 256, GEMM_SMEM>>>(
            aug3 + (size_t)t * NN * KA, KA, w2ih3, KA, gi, G3, KA / 64);
        if (t == 0) {
            gru_gates_kernel<true><<<NN, 256>>>(
                gi, nullptr, nullptr, 0, feats3, KD, g2_bih, g2_bhh);
        } else {
            gemm3_kernel<<<ggrid, 256, GEMM_SMEM>>>(
                feats3 + (size_t)(t - 1) * KH, KD, w2hh3, KH, gh, G3, KH / 64);
            gru_gates_kernel<false><<<NN, 256>>>(
                gi, gh,
                feats3 + (size_t)(t - 1) * KH, KD,
                feats3 + (size_t)t * KH, KD, g2_bih, g2_bhh);
        }
    }

    // 6. Decoder GEMM into d_out, then fused bias+LN+leaky
    gemm3_kernel<<<dim3(OUTD / 128, NN / 128), 256, GEMM_SMEM>>>(
        feats3, KD, dec3, KD, out, OUTD, KD / 64);
    ln_leaky_kernel<<<NN, 256>>>(out, dec_b, ln_w, ln_b);
}

// round 8
// speedup vs baseline: 2.3617x; 1.0012x over previous
#include <cuda_runtime.h>
#include <cuda_bf16.h>
#include <math.h>
#include <stdint.h>

// ---------------------------------------------------------------------------
// Problem constants
// ---------------------------------------------------------------------------
#define NN 65536
#define CIN 8
#define COUT 128
#define HH 256
#define OUTD 256
#define TT 5
#define G3 768             // 3*H (gate dim)
#define K1 (3*COUT)        // 384   expanded K: x only
#define KH (3*HH)          // 768   expanded K: hidden
#define KA (3*(COUT+HH))   // 1152  expanded K: [x | h1]
#define KD (3*TT*HH)       // 3840  expanded K: decoder input

// ---------------------------------------------------------------------------
// Device scratch — total ~1.67 GB (must stay < 2 GiB or host link fails
// with GOTPCREL relocation overflow; learned R5)
// ---------------------------------------------------------------------------
__device__ __nv_bfloat16  g_aug3[(size_t)TT * NN * KA];     // 755 MB [t*N+n][1152] triplets: x | h1
__device__ __nv_bfloat16  g_feats3[(size_t)NN * KD];        // 503 MB [n][3840] GRU2 states, decoder layout
__device__ float          g_gi[(size_t)NN * G3];            // 201 MB per-step gi (also aliases conv out)
__device__ float          g_gh[(size_t)NN * G3];            // 201 MB per-step gh
__device__ float          g_part[2 * 2048 * COUT];
__device__ float          g_bnscale[COUT];
__device__ float          g_bnshift[COUT];
__device__ __nv_bfloat16  g_w1ih3[G3 * K1];
__device__ __nv_bfloat16  g_w1hh3[G3 * KH];
__device__ __nv_bfloat16  g_w2ih3[G3 * KA];
__device__ __nv_bfloat16  g_w2hh3[G3 * KH];
__device__ __nv_bfloat16  g_dec3[OUTD * KD];

// Conv fp32 output aliases g_gi: 5*65536*128 floats (41.9M) < 50.3M capacity.
// bn_relu_expand consumes it before the first GEMM overwrites g_gi.

// ---------------------------------------------------------------------------
// Helpers (baseline PTX only: cp.async / ldmatrix / mma.sync — no tcgen05,
// which is sm_100a-only and the harness compiles for base sm_100)
// ---------------------------------------------------------------------------
__device__ __forceinline__ uint32_t smem_u32(const void* p) {
    uint32_t a;
    asm("{ .reg .u64 t; cvta.to.shared.u64 t, %1; cvt.u32.u64 %0, t; }"
        : "=r"(a) : "l"(p));
    return a;
}
#define SW128(x) ((x) ^ (((x) >> 3) & 0x70))

#define CP_ASYNC16(dst, src) \
    asm volatile("cp.async.cg.shared.global [%0], [%1], 16;" \
        :: "r"(dst), "l"(src) : "memory")
#define CP_COMMIT()  asm volatile("cp.async.commit_group;" ::: "memory")
#define CP_WAIT1()   asm volatile("cp.async.wait_group 1;" ::: "memory")

#define LDMATRIX_X4(r0, r1, r2, r3, addr) \
    asm volatile("ldmatrix.sync.aligned.m8n8.x4.shared.b16 {%0,%1,%2,%3}, [%4];" \
        : "=r"(r0), "=r"(r1), "=r"(r2), "=r"(r3) : "r"(addr))
// B smem is [n][k] with k contiguous == col-major KxN: NON-trans ldmatrix
// yields the b0/b1 fragment directly (R6 fix: .trans here was the bug).
#define LDMATRIX_X2(r0, r1, addr) \
    asm volatile("ldmatrix.sync.aligned.m8n8.x2.shared.b16 {%0,%1}, [%2];" \
        : "=r"(r0), "=r"(r1) : "r"(addr))

#define MMA_BF16(d, a, b) \
    asm volatile("mma.sync.aligned.m16n8k16.row.col.f32.bf16.bf16.f32 " \
        "{%0,%1,%2,%3}, {%4,%5,%6,%7}, {%8,%9}, {%0,%1,%2,%3};" \
        : "+f"((d)[0]), "+f"((d)[1]), "+f"((d)[2]), "+f"((d)[3]) \
        : "r"((a)[0]), "r"((a)[1]), "r"((a)[2]), "r"((a)[3]), \
          "r"((b)[0]), "r"((b)[1]))

// ---------------------------------------------------------------------------
// HMMA GEMM:  C[m][n] = sum_k A[m][k]*B[n][k]   (both K-major bf16, C fp32)
// CTA tile 128x128x64, 3-stage cp.async pipeline, SW128 swizzle + ldmatrix.
// Grid: (Ntotal/128, Mtotal/128). K = ktiles*64.
// ---------------------------------------------------------------------------
#define STAGE_BYTES 32768                // A 16KB + B 16KB
#define GEMM_SMEM   (3 * STAGE_BYTES + 1024)

__global__ void __launch_bounds__(256, 2) gemm3_kernel(
    const __nv_bfloat16* __restrict__ A, int lda,
    const __nv_bfloat16* __restrict__ B, int ldb,
    float* __restrict__ C, int ldc, int ktiles)
{
    extern __shared__ char smem_raw[];
    const uint32_t sb = (smem_u32(smem_raw) + 1023u) & ~1023u;

    const int tid  = threadIdx.x;
    const int wid  = tid >> 5;
    const int lane = tid & 31;
    const int wm = wid & 1;              // 2 M-warps  (64 rows each)
    const int wn = wid >> 1;             // 4 N-warps  (32 cols each)
    const size_t m0 = (size_t)blockIdx.y * 128;
    const int    n0 = blockIdx.x * 128;

    float acc[4][4][4];
    #pragma unroll
    for (int i = 0; i < 4; i++)
        #pragma unroll
        for (int j = 0; j < 4; j++)
            #pragma unroll
            for (int v = 0; v < 4; v++) acc[i][j][v] = 0.f;

    // ---- prologue: stages 0,1 ----
    #pragma unroll
    for (int s = 0; s < 2; s++) {
        const uint32_t sA = sb + s * STAGE_BYTES;
        const uint32_t sB = sA + 16384u;
        #pragma unroll
        for (int i = 0; i < 4; i++) {
            const int idx = tid + (i << 8);
            const int r = idx >> 3, c = idx & 7;
            const __nv_bfloat16* ga = A + (m0 + r) * (size_t)lda + (size_t)s * 64 + c * 8;
            const __nv_bfloat16* gb = B + (size_t)(n0 + r) * (size_t)ldb + (size_t)s * 64 + c * 8;
            CP_ASYNC16(sA + (uint32_t)SW128(r * 128 + c * 16), ga);
            CP_ASYNC16(sB + (uint32_t)SW128(r * 128 + c * 16), gb);
        }
        CP_COMMIT();
    }

    for (int kt = 0; kt < ktiles; kt++) {
        CP_WAIT1();
        __syncthreads();

        const uint32_t sA = sb + (uint32_t)(kt % 3) * STAGE_BYTES;
        const uint32_t sB = sA + 16384u;

        // ---- compute tile kt ----
        #pragma unroll
        for (int kc = 0; kc < 4; kc++) {
            uint32_t afr[4][4];
            uint32_t bfr[4][2];
            #pragma unroll
            for (int im = 0; im < 4; im++) {
                const int m  = wm * 64 + im * 16 + ((lane >> 3) & 1) * 8 + (lane & 7);
                const int kk = kc * 16 + (lane >> 4) * 8;
                const uint32_t addr = sA + (uint32_t)SW128(m * 128 + kk * 2);
                LDMATRIX_X4(afr[im][0], afr[im][1], afr[im][2], afr[im][3], addr);
            }
            #pragma unroll
            for (int in_ = 0; in_ < 4; in_++) {
                const int n  = wn * 32 + in_ * 8 + (lane & 7);
                const int kk = kc * 16 + ((lane >> 3) & 1) * 8;
                const uint32_t addr = sB + (uint32_t)SW128(n * 128 + kk * 2);
                LDMATRIX_X2(bfr[in_][0], bfr[in_][1], addr);
            }
            #pragma unroll
            for (int im = 0; im < 4; im++)
                #pragma unroll
                for (int in_ = 0; in_ < 4; in_++)
                    MMA_BF16(acc[im][in_], afr[im], bfr[in_]);
        }

        // ---- issue stage kt+2 ----
        if (kt + 2 < ktiles) {
            const int s = kt + 2;
            const uint32_t dA = sb + (uint32_t)(s % 3) * STAGE_BYTES;
            const uint32_t dB = dA + 16384u;
            #pragma unroll
            for (int i = 0; i < 4; i++) {
                const int idx = tid + (i << 8);
                const int r = idx >> 3, c = idx & 7;
                const __nv_bfloat16* ga = A + (m0 + r) * (size_t)lda + (size_t)s * 64 + c * 8;
                const __nv_bfloat16* gb = B + (size_t)(n0 + r) * (size_t)ldb + (size_t)s * 64 + c * 8;
                CP_ASYNC16(dA + (uint32_t)SW128(r * 128 + c * 16), ga);
                CP_ASYNC16(dB + (uint32_t)SW128(r * 128 + c * 16), gb);
            }
        }
        CP_COMMIT();
    }

    // ---- epilogue ----
    const int grp = lane >> 2;
    const int tig = lane & 3;
    #pragma unroll
    for (int im = 0; im < 4; im++) {
        const size_t row = m0 + wm * 64 + im * 16 + grp;
        #pragma unroll
        for (int in_ = 0; in_ < 4; in_++) {
            const int col = n0 + wn * 32 + in_ * 8 + 2 * tig;
            *reinterpret_cast<float2*>(C + row * (size_t)ldc + col) =
                make_float2(acc[im][in_][0], acc[im][in_][1]);
            *reinterpret_cast<float2*>(C + (row + 8) * (size_t)ldc + col) =
                make_float2(acc[im][in_][2], acc[im][in_][3]);
        }
    }
}

// ---------------------------------------------------------------------------
// Conv1d(k=3,pad=1) + BN partial stats (fp32). Output -> g_gi (aliased).
// ---------------------------------------------------------------------------
__global__ __launch_bounds__(128) void conv_kernel(
    const float* __restrict__ tracks, const float* __restrict__ conv_w)
{
    __shared__ float s_in[32 * CIN * TT];
    const int c  = threadIdx.x;
    const int n0 = blockIdx.x * 32;

    float w[CIN * 3];
    #pragma unroll
    for (int j = 0; j < CIN * 3; j++) w[j] = conv_w[c * (CIN * 3) + j];

    for (int idx = c; idx < 32 * CIN * TT; idx += 128)
        s_in[idx] = tracks[(size_t)n0 * (CIN * TT) + idx];
    __syncthreads();

    float sum = 0.f, sq = 0.f;
    for (int nl = 0; nl < 32; nl++) {
        const float* in = &s_in[nl * CIN * TT];
        #pragma unroll
        for (int t = 0; t < TT; t++) {
            float a = 0.f;
            #pragma unroll
            for (int ci = 0; ci < CIN; ci++) {
                #pragma unroll
                for (int k = 0; k < 3; k++) {
                    const int tt = t + k - 1;
                    if (tt >= 0 && tt < TT)
                        a += in[ci * TT + tt] * w[ci * 3 + k];
                }
            }
            g_gi[((size_t)t * NN + n0 + nl) * COUT + c] = a;
            sum += a; sq += a * a;
        }
    }
    g_part[blockIdx.x * COUT + c] = sum;
    g_part[2048 * COUT + blockIdx.x * COUT + c] = sq;
}

__global__ void bn_finalize_kernel(const float* __restrict__ gamma,
                                   const float* __restrict__ beta)
{
    const int c = threadIdx.x;
    double s = 0.0, q = 0.0;
    for (int b = 0; b < 2048; b++) {
        s += (double)g_part[b * COUT + c];
        q += (double)g_part[2048 * COUT + b * COUT + c];
    }
    const double inv = 1.0 / ((double)TT * (double)NN);
    const double mean = s * inv;
    const double var  = q * inv - mean * mean;
    const float sc = gamma[c] * rsqrtf((float)var + 1e-5f);
    g_bnscale[c] = sc;
    g_bnshift[c] = beta[c] - (float)mean * sc;
}

// BN + ReLU on conv out (in g_gi), expand to {hi, lo, hi} triplets into
// g_aug3 cols [0, 384). Must run before any GEMM writes g_gi.
__global__ __launch_bounds__(256) void bn_relu_expand_kernel()
{
    const size_t i = (size_t)blockIdx.x * 256 + threadIdx.x;
    const int c = (int)(i & (COUT - 1));
    const size_t m = i >> 7;
    float v = g_gi[i] * g_bnscale[c] + g_bnshift[c];
    v = v > 0.f ? v : 0.f;
    const __nv_bfloat16 hi = __float2bfloat16_rn(v);
    const __nv_bfloat16 lo = __float2bfloat16_rn(v - __bfloat162float(hi));
    __nv_bfloat16* o = g_aug3 + m * KA + 3 * c;
    o[0] = hi; o[1] = lo; o[2] = hi;
}

// Weight expand: fp32 -> {hi, hi, lo} triplets (flat; preserves row-major)
__global__ __launch_bounds__(256) void expand_weight_kernel(
    const float* __restrict__ w, __nv_bfloat16* __restrict__ out, int n)
{
    const int i = blockIdx.x * 256 + threadIdx.x;
    if (i >= n) return;
    const float v = w[i];
    const __nv_bfloat16 hi = __float2bfloat16_rn(v);
    const __nv_bfloat16 lo = __float2bfloat16_rn(v - __bfloat162float(hi));
    out[3 * i + 0] = hi; out[3 * i + 1] = hi; out[3 * i + 2] = lo;
}

// ---------------------------------------------------------------------------
// GRU gates. fp32 gi/gh; h_prev read from triplets (hi+lo); writes triplets.
// ---------------------------------------------------------------------------
template<bool FIRST>
__global__ __launch_bounds__(256) void gru_gates_kernel(
    const float* __restrict__ gi, const float* __restrict__ gh,
    const __nv_bfloat16* __restrict__ hprev, size_t hp_ld,
    __nv_bfloat16* __restrict__ hout, size_t ho_ld,
    const float* __restrict__ bih, const float* __restrict__ bhh)
{
    const size_t n = blockIdx.x;
    const int c = threadIdx.x;
    const float* gir = gi + n * G3;
    const float ir  = gir[c]       + bih[c];
    const float iz  = gir[c + 256] + bih[c + 256];
    const float in_ = gir[c + 512] + bih[c + 512];
    float hr, hz, hn, h;
    if (FIRST) {
        hr = bhh[c]; hz = bhh[c + 256]; hn = bhh[c + 512]; h = 0.f;
    } else {
        const float* ghr = gh + n * G3;
        hr = ghr[c]       + bhh[c];
        hz = ghr[c + 256] + bhh[c + 256];
        hn = ghr[c + 512] + bhh[c + 512];
        const __nv_bfloat16* hp = hprev + n * hp_ld + 3 * c;
        h = __bfloat162float(hp[0]) + __bfloat162float(hp[1]);
    }
    const float r = 1.f / (1.f + expf(-(ir + hr)));
    const float z = 1.f / (1.f + expf(-(iz + hz)));
    const float nn2 = tanhf(in_ + r * hn);
    const float ho = (1.f - z) * nn2 + z * h;
    const __nv_bfloat16 hi = __float2bfloat16_rn(ho);
    const __nv_bfloat16 lo = __float2bfloat16_rn(ho - __bfloat162float(hi));
    __nv_bfloat16* o = hout + n * ho_ld + 3 * c;
    o[0] = hi; o[1] = lo; o[2] = hi;
}

// ---------------------------------------------------------------------------
// bias + LayerNorm + leaky ReLU in place on d_out
// ---------------------------------------------------------------------------
__global__ __launch_bounds__(256) void ln_leaky_kernel(
    float* __restrict__ y, const float* __restrict__ dec_b,
    const float* __restrict__ ln_w, const float* __restrict__ ln_b)
{
    __shared__ float red[256];
    const size_t r = blockIdx.x;
    const int c = threadIdx.x;
    const float v = y[r * OUTD + c] + dec_b[c];

    red[c] = v;
    __syncthreads();
    #pragma unroll
    for (int s = 128; s > 0; s >>= 1) {
        if (c < s) red[c] += red[c + s];
        __syncthreads();
    }
    const float mean = red[0] * (1.f / OUTD);
    __syncthreads();

    const float d = v - mean;
    red[c] = d * d;
    __syncthreads();
    #pragma unroll
    for (int s = 128; s > 0; s >>= 1) {
        if (c < s) red[c] += red[c + s];
        __syncthreads();
    }
    const float var = red[0] * (1.f / OUTD);

    const float o = d * rsqrtf(var + 1e-5f) * ln_w[c] + ln_b[c];
    y[r * OUTD + c] = o >= 0.f ? o : 0.05f * o;
}

// ---------------------------------------------------------------------------
// Launch
// ---------------------------------------------------------------------------
extern "C" void kernel_launch(void* const* d_in, const int* in_sizes, int n_in,
                              void* d_out, int out_size)
{
    const float* tracks   = (const float*)d_in[0];
    const float* conv_w   = (const float*)d_in[1];
    const float* bn_gamma = (const float*)d_in[2];
    const float* bn_beta  = (const float*)d_in[3];
    const float* g1_wih   = (const float*)d_in[4];
    const float* g1_whh   = (const float*)d_in[5];
    const float* g1_bih   = (const float*)d_in[6];
    const float* g1_bhh   = (const float*)d_in[7];
    const float* g2_wih   = (const float*)d_in[8];
    const float* g2_whh   = (const float*)d_in[9];
    const float* g2_bih   = (const float*)d_in[10];
    const float* g2_bhh   = (const float*)d_in[11];
    const float* dec_w    = (const float*)d_in[12];
    const float* dec_b    = (const float*)d_in[13];
    const float* ln_w     = (const float*)d_in[14];
    const float* ln_b     = (const float*)d_in[15];
    float* out = (float*)d_out;

    __nv_bfloat16 *aug3, *feats3, *w1ih3, *w1hh3, *w2ih3, *w2hh3, *dec3;
    float *gi, *gh;
    cudaGetSymbolAddress((void**)&aug3,   g_aug3);
    cudaGetSymbolAddress((void**)&feats3, g_feats3);
    cudaGetSymbolAddress((void**)&gi,     g_gi);
    cudaGetSymbolAddress((void**)&gh,     g_gh);
    cudaGetSymbolAddress((void**)&w1ih3,  g_w1ih3);
    cudaGetSymbolAddress((void**)&w1hh3,  g_w1hh3);
    cudaGetSymbolAddress((void**)&w2ih3,  g_w2ih3);
    cudaGetSymbolAddress((void**)&w2hh3,  g_w2hh3);
    cudaGetSymbolAddress((void**)&dec3,   g_dec3);

    cudaFuncSetAttribute(gemm3_kernel,
                         cudaFuncAttributeMaxDynamicSharedMemorySize, GEMM_SMEM);

    // 0. Expand weights to bf16 triplets
    expand_weight_kernel<<<(G3 * COUT + 255) / 256, 256>>>(g1_wih, w1ih3, G3 * COUT);
    expand_weight_kernel<<<(G3 * HH + 255) / 256, 256>>>(g1_whh, w1hh3, G3 * HH);
    expand_weight_kernel<<<(G3 * (COUT + HH) + 255) / 256, 256>>>(g2_wih, w2ih3, G3 * (COUT + HH));
    expand_weight_kernel<<<(G3 * HH + 255) / 256, 256>>>(g2_whh, w2hh3, G3 * HH);
    expand_weight_kernel<<<(OUTD * TT * HH + 255) / 256, 256>>>(dec_w, dec3, OUTD * TT * HH);

    // 1. Conv (out -> g_gi alias) + BN stats + BN/ReLU/expand into aug3[:, 0:384)
    conv_kernel<<<NN / 32, 128>>>(tracks, conv_w);
    bn_finalize_kernel<<<1, 128>>>(bn_gamma, bn_beta);
    bn_relu_expand_kernel<<<((size_t)TT * NN * COUT) / 256, 256>>>();

    const dim3 ggrid(G3 / 128, NN / 128);   // per-step GEMM grid (3072 CTAs)

    // 2+3. GRU1 backward over t (per-step gi GEMM; first step has no gh GEMM)
    for (int t = TT - 1; t >= 0; t--) {
        gemm3_kernel<<<ggrid, 256, GEMM_SMEM>>>(
            aug3 + (size_t)t * NN * KA, KA, w1ih3, K1, gi, G3, K1 / 64);
        if (t == TT - 1) {
            gru_gates_kernel<true><<<NN, 256>>>(
                gi, nullptr, nullptr, 0,
                aug3 + (size_t)t * NN * KA + K1, KA, g1_bih, g1_bhh);
        } else {
            gemm3_kernel<<<ggrid, 256, GEMM_SMEM>>>(
                aug3 + (size_t)(t + 1) * NN * KA + K1, KA, w1hh3, KH, gh, G3, KH / 64);
            gru_gates_kernel<false><<<NN, 256>>>(
                gi, gh,
                aug3 + (size_t)(t + 1) * NN * KA + K1, KA,
                aug3 + (size_t)t * NN * KA + K1, KA, g1_bih, g1_bhh);
        }
    }

    // 4+5. GRU2 forward over t (per-step gi2 GEMM, K=1152); hidden written
    //      straight into decoder layout feats3[n][t*768 .. t*768+768)
    for (int t = 0; t < TT; t++) {
        gemm3_kernel<<<ggrid, 256, GEMM_SMEM>>>(
            aug3 + (size_t)t * NN * KA, KA, w2ih3, KA, gi, G3, KA / 64);
        if (t == 0) {
            gru_gates_kernel<true><<<NN, 256>>>(
                gi, nullptr, nullptr, 0, feats3, KD, g2_bih, g2_bhh);
        } else {
            gemm3_kernel<<<ggrid, 256, GEMM_SMEM>>>(
                feats3 + (size_t)(t - 1) * KH, KD, w2hh3, KH, gh, G3, KH / 64);
            gru_gates_kernel<false><<<NN, 256>>>(
                gi, gh,
                feats3 + (size_t)(t - 1) * KH, KD,
                feats3 + (size_t)t * KH, KD, g2_bih, g2_bhh);
        }
    }

    // 6. Decoder GEMM into d_out, then fused bias+LN+leaky
    gemm3_kernel<<<dim3(OUTD / 128, NN / 128), 256, GEMM_SMEM>>>(
        feats3, KD, dec3, KD, out, OUTD, KD / 64);
    ln_leaky_kernel<<<NN, 256>>>(out, dec_b, ln_w, ln_b);
}

// round 10
// speedup vs baseline: 2.3799x; 1.0077x over previous
#include <cuda_runtime.h>
#include <cuda_bf16.h>
#include <math.h>
#include <stdint.h>

// ---------------------------------------------------------------------------
// Problem constants
// ---------------------------------------------------------------------------
#define NN 65536
#define CIN 8
#define COUT 128
#define HH 256
#define OUTD 256
#define TT 5
#define G3 768             // 3*H (gate dim)
#define K1 (3*COUT)        // 384   expanded K: x only
#define KH (3*HH)          // 768   expanded K: hidden
#define KA (3*(COUT+HH))   // 1152  expanded K: [x | h1]
#define KD (3*TT*HH)       // 3840  expanded K: decoder input

// ---------------------------------------------------------------------------
// Device scratch — ~1.47 GB (< 2 GiB or GOTPCREL link failure; learned R5)
// ---------------------------------------------------------------------------
__device__ __align__(256) __nv_bfloat16  g_aug3[(size_t)TT * NN * KA];   // 755 MB triplets: x | h1
__device__ __align__(256) __nv_bfloat16  g_feats3[(size_t)NN * KD];      // 503 MB GRU2 states
__device__ __align__(256) float          g_gi[(size_t)NN * G3];          // 201 MB per-step gi (aliases conv out)
__device__ __align__(256) float          g_part[2 * 2048 * COUT];
__device__ float          g_bnscale[COUT];
__device__ float          g_bnshift[COUT];
__device__ __align__(256) __nv_bfloat16  g_w1ih3[G3 * K1];
__device__ __align__(256) __nv_bfloat16  g_w1hh3[G3 * KH];
__device__ __align__(256) __nv_bfloat16  g_w2ih3[G3 * KA];
__device__ __align__(256) __nv_bfloat16  g_w2hh3[G3 * KH];
__device__ __align__(256) __nv_bfloat16  g_dec3[OUTD * KD];

// ---------------------------------------------------------------------------
// Helpers (baseline PTX: cp.async / ldmatrix / mma.sync — target is sm_100)
// ---------------------------------------------------------------------------
__device__ __forceinline__ uint32_t smem_u32(const void* p) {
    uint32_t a;
    asm("{ .reg .u64 t; cvta.to.shared.u64 t, %1; cvt.u32.u64 %0, t; }"
        : "=r"(a) : "l"(p));
    return a;
}
#define SW128(x) ((x) ^ (((x) >> 3) & 0x70))

#define CP_ASYNC16(dst, src) \
    asm volatile("cp.async.cg.shared.global [%0], [%1], 16;" \
        :: "r"(dst), "l"(src) : "memory")
#define CP_COMMIT()  asm volatile("cp.async.commit_group;" ::: "memory")
#define CP_WAIT1()   asm volatile("cp.async.wait_group 1;" ::: "memory")

#define LDMATRIX_X4(r0, r1, r2, r3, addr) \
    asm volatile("ldmatrix.sync.aligned.m8n8.x4.shared.b16 {%0,%1,%2,%3}, [%4];" \
        : "=r"(r0), "=r"(r1), "=r"(r2), "=r"(r3) : "r"(addr))
#define LDMATRIX_X2(r0, r1, addr) \
    asm volatile("ldmatrix.sync.aligned.m8n8.x2.shared.b16 {%0,%1}, [%2];" \
        : "=r"(r0), "=r"(r1) : "r"(addr))

#define MMA_BF16(d, a, b) \
    asm volatile("mma.sync.aligned.m16n8k16.row.col.f32.bf16.bf16.f32 " \
        "{%0,%1,%2,%3}, {%4,%5,%6,%7}, {%8,%9}, {%0,%1,%2,%3};" \
        : "+f"((d)[0]), "+f"((d)[1]), "+f"((d)[2]), "+f"((d)[3]) \
        : "r"((a)[0]), "r"((a)[1]), "r"((a)[2]), "r"((a)[3]), \
          "r"((b)[0]), "r"((b)[1]))

__device__ __forceinline__ float sigf(float x) { return 1.f / (1.f + expf(-x)); }

// ---------------------------------------------------------------------------
// HMMA GEMM:  C[m][n] = sum_k A[m][k]*B[n][k]   (both K-major bf16, C fp32)
// CTA tile 128x128x64, 3-stage cp.async, SW128 + ldmatrix.
// EXACT R8-proven version (B fragments via X2 ldmatrix).
// ---------------------------------------------------------------------------
#define STAGE_BYTES 32768                // A 16KB + B 16KB
#define GEMM_SMEM   (3 * STAGE_BYTES + 1024)

__global__ void __launch_bounds__(256, 2) gemm3_kernel(
    const __nv_bfloat16* __restrict__ A, int lda,
    const __nv_bfloat16* __restrict__ B, int ldb,
    float* __restrict__ C, int ldc, int ktiles)
{
    extern __shared__ char smem_raw[];
    const uint32_t sb = (smem_u32(smem_raw) + 1023u) & ~1023u;

    const int tid  = threadIdx.x;
    const int wid  = tid >> 5;
    const int lane = tid & 31;
    const int wm = wid & 1;
    const int wn = wid >> 1;
    const size_t m0 = (size_t)blockIdx.y * 128;
    const int    n0 = blockIdx.x * 128;

    float acc[4][4][4];
    #pragma unroll
    for (int i = 0; i < 4; i++)
        #pragma unroll
        for (int j = 0; j < 4; j++)
            #pragma unroll
            for (int v = 0; v < 4; v++) acc[i][j][v] = 0.f;

    #pragma unroll
    for (int s = 0; s < 2; s++) {
        const uint32_t sA = sb + s * STAGE_BYTES;
        const uint32_t sB = sA + 16384u;
        #pragma unroll
        for (int i = 0; i < 4; i++) {
            const int idx = tid + (i << 8);
            const int r = idx >> 3, c = idx & 7;
            const __nv_bfloat16* ga = A + (m0 + r) * (size_t)lda + (size_t)s * 64 + c * 8;
            const __nv_bfloat16* gb = B + (size_t)(n0 + r) * (size_t)ldb + (size_t)s * 64 + c * 8;
            CP_ASYNC16(sA + (uint32_t)SW128(r * 128 + c * 16), ga);
            CP_ASYNC16(sB + (uint32_t)SW128(r * 128 + c * 16), gb);
        }
        CP_COMMIT();
    }

    for (int kt = 0; kt < ktiles; kt++) {
        CP_WAIT1();
        __syncthreads();

        const uint32_t sA = sb + (uint32_t)(kt % 3) * STAGE_BYTES;
        const uint32_t sB = sA + 16384u;

        #pragma unroll
        for (int kc = 0; kc < 4; kc++) {
            uint32_t afr[4][4];
            uint32_t bfr[4][2];
            #pragma unroll
            for (int im = 0; im < 4; im++) {
                const int m  = wm * 64 + im * 16 + ((lane >> 3) & 1) * 8 + (lane & 7);
                const int kk = kc * 16 + (lane >> 4) * 8;
                LDMATRIX_X4(afr[im][0], afr[im][1], afr[im][2], afr[im][3],
                            sA + (uint32_t)SW128(m * 128 + kk * 2));
            }
            #pragma unroll
            for (int in_ = 0; in_ < 4; in_++) {
                const int n  = wn * 32 + in_ * 8 + (lane & 7);
                const int kk = kc * 16 + ((lane >> 3) & 1) * 8;
                LDMATRIX_X2(bfr[in_][0], bfr[in_][1],
                            sB + (uint32_t)SW128(n * 128 + kk * 2));
            }
            #pragma unroll
            for (int im = 0; im < 4; im++)
                #pragma unroll
                for (int in_ = 0; in_ < 4; in_++)
                    MMA_BF16(acc[im][in_], afr[im], bfr[in_]);
        }

        if (kt + 2 < ktiles) {
            const int s = kt + 2;
            const uint32_t dA = sb + (uint32_t)(s % 3) * STAGE_BYTES;
            const uint32_t dB = dA + 16384u;
            #pragma unroll
            for (int i = 0; i < 4; i++) {
                const int idx = tid + (i << 8);
                const int r = idx >> 3, c = idx & 7;
                const __nv_bfloat16* ga = A + (m0 + r) * (size_t)lda + (size_t)s * 64 + c * 8;
                const __nv_bfloat16* gb = B + (size_t)(n0 + r) * (size_t)ldb + (size_t)s * 64 + c * 8;
                CP_ASYNC16(dA + (uint32_t)SW128(r * 128 + c * 16), ga);
                CP_ASYNC16(dB + (uint32_t)SW128(r * 128 + c * 16), gb);
            }
        }
        CP_COMMIT();
    }

    const int grp = lane >> 2;
    const int tig = lane & 3;
    #pragma unroll
    for (int im = 0; im < 4; im++) {
        const size_t row = m0 + wm * 64 + im * 16 + grp;
        #pragma unroll
        for (int in_ = 0; in_ < 4; in_++) {
            const int col = n0 + wn * 32 + in_ * 8 + 2 * tig;
            *reinterpret_cast<float2*>(C + row * (size_t)ldc + col) =
                make_float2(acc[im][in_][0], acc[im][in_][1]);
            *reinterpret_cast<float2*>(C + (row + 8) * (size_t)ldc + col) =
                make_float2(acc[im][in_][2], acc[im][in_][3]);
        }
    }
}

// ---------------------------------------------------------------------------
// Fused hidden-GEMM + GRU gates.
// gh = h_prev @ Whh^T for a 128x96 tile; 96 cols = 4 N-warps x (3 gates x
// 8 channels), B rows gate-strided from Whh so each thread holds r/z/n of the
// same channel. Epilogue does exact fp32 gate math and writes h_t triplets.
// A tile = 128 rows x 128B = 1024 16B-chunks = 4/thread (R9 bug: was 8/thread
// -> OOB global reads at rows m0+128..m0+255).
// K = KH = 768 fixed (12 k-tiles). Grid: (HH/32 = 8, M/128).
// ---------------------------------------------------------------------------
#define FSTAGE_BYTES (16384 + 12288)     // A 16KB + B 12KB (96 rows x 128B)
#define FUSED_SMEM   (3 * FSTAGE_BYTES + 1024)

__global__ void __launch_bounds__(256, 2) gru_fused_kernel(
    const __nv_bfloat16* __restrict__ A, int lda,      // h_prev triplets
    const __nv_bfloat16* __restrict__ Bw,              // whh3 [768][KH]
    const float* __restrict__ gi,                      // [M][768]
    __nv_bfloat16* __restrict__ hout, int ho_ld,
    const float* __restrict__ bih, const float* __restrict__ bhh)
{
    extern __shared__ char smem_raw[];
    const uint32_t sb = (smem_u32(smem_raw) + 1023u) & ~1023u;

    const int tid  = threadIdx.x;
    const int wid  = tid >> 5;
    const int lane = tid & 31;
    const int wm = wid & 1;              // 2 M-warps (64 rows)
    const int wn = wid >> 1;             // 4 N-warps (24 cols: 3 gates x 8 ch)
    const size_t m0 = (size_t)blockIdx.y * 128;
    const int chblk = blockIdx.x;        // 32 channels per block

    const int KT = KH / 64;              // 12

    float acc[4][3][4];
    #pragma unroll
    for (int i = 0; i < 4; i++)
        #pragma unroll
        for (int g = 0; g < 3; g++)
            #pragma unroll
            for (int v = 0; v < 4; v++) acc[i][g][v] = 0.f;

    // loaders: A 1024 chunks (4/thread), B 768 chunks (3/thread)
    #pragma unroll
    for (int s = 0; s < 2; s++) {
        const uint32_t sA = sb + s * FSTAGE_BYTES;
        const uint32_t sB = sA + 16384u;
        #pragma unroll
        for (int i = 0; i < 4; i++) {
            const int idx = tid + (i << 8);
            const int r = idx >> 3, c = idx & 7;
            const __nv_bfloat16* ga = A + (m0 + r) * (size_t)lda + (size_t)s * 64 + c * 8;
            CP_ASYNC16(sA + (uint32_t)SW128(r * 128 + c * 16), ga);
        }
        #pragma unroll
        for (int i = 0; i < 3; i++) {
            const int idx = tid + (i << 8);
            const int j = idx >> 3, c = idx & 7;
            const int jw = j / 24, rem = j % 24;
            const int grow = (rem / 8) * 256 + chblk * 32 + jw * 8 + (rem & 7);
            const __nv_bfloat16* gb = Bw + (size_t)grow * KH + (size_t)s * 64 + c * 8;
            CP_ASYNC16(sB + (uint32_t)SW128(j * 128 + c * 16), gb);
        }
        CP_COMMIT();
    }

    for (int kt = 0; kt < KT; kt++) {
        CP_WAIT1();
        __syncthreads();

        const uint32_t sA = sb + (uint32_t)(kt % 3) * FSTAGE_BYTES;
        const uint32_t sB = sA + 16384u;

        #pragma unroll
        for (int kc = 0; kc < 4; kc++) {
            uint32_t afr[4][4];
            uint32_t bfr[3][2];
            #pragma unroll
            for (int im = 0; im < 4; im++) {
                const int m  = wm * 64 + im * 16 + ((lane >> 3) & 1) * 8 + (lane & 7);
                const int kk = kc * 16 + (lane >> 4) * 8;
                LDMATRIX_X4(afr[im][0], afr[im][1], afr[im][2], afr[im][3],
                            sA + (uint32_t)SW128(m * 128 + kk * 2));
            }
            #pragma unroll
            for (int g = 0; g < 3; g++) {
                const int j  = wn * 24 + g * 8 + (lane & 7);
                const int kk = kc * 16 + ((lane >> 3) & 1) * 8;
                LDMATRIX_X2(bfr[g][0], bfr[g][1],
                            sB + (uint32_t)SW128(j * 128 + kk * 2));
            }
            #pragma unroll
            for (int im = 0; im < 4; im++)
                #pragma unroll
                for (int g = 0; g < 3; g++)
                    MMA_BF16(acc[im][g], afr[im], bfr[g]);
        }

        if (kt + 2 < KT) {
            const int s = kt + 2;
            const uint32_t dA = sb + (uint32_t)(s % 3) * FSTAGE_BYTES;
            const uint32_t dB = dA + 16384u;
            #pragma unroll
            for (int i = 0; i < 4; i++) {
                const int idx = tid + (i << 8);
                const int r = idx >> 3, c = idx & 7;
                const __nv_bfloat16* ga = A + (m0 + r) * (size_t)lda + (size_t)s * 64 + c * 8;
                CP_ASYNC16(dA + (uint32_t)SW128(r * 128 + c * 16), ga);
            }
            #pragma unroll
            for (int i = 0; i < 3; i++) {
                const int idx = tid + (i << 8);
                const int j = idx >> 3, c = idx & 7;
                const int jw = j / 24, rem = j % 24;
                const int grow = (rem / 8) * 256 + chblk * 32 + jw * 8 + (rem & 7);
                const __nv_bfloat16* gb = Bw + (size_t)grow * KH + (size_t)s * 64 + c * 8;
                CP_ASYNC16(dB + (uint32_t)SW128(j * 128 + c * 16), gb);
            }
        }
        CP_COMMIT();
    }

    // ---- fused gate epilogue ----
    const int grp = lane >> 2;
    const int tig = lane & 3;
    const int ch0 = chblk * 32 + wn * 8 + 2 * tig;    // channel pair base
    const float bi_r0 = bih[ch0],       bi_r1 = bih[ch0 + 1];
    const float bi_z0 = bih[256 + ch0], bi_z1 = bih[256 + ch0 + 1];
    const float bi_n0 = bih[512 + ch0], bi_n1 = bih[512 + ch0 + 1];
    const float bh_r0 = bhh[ch0],       bh_r1 = bhh[ch0 + 1];
    const float bh_z0 = bhh[256 + ch0], bh_z1 = bhh[256 + ch0 + 1];
    const float bh_n0 = bhh[512 + ch0], bh_n1 = bhh[512 + ch0 + 1];

    #pragma unroll
    for (int im = 0; im < 4; im++) {
        #pragma unroll
        for (int half = 0; half < 2; half++) {
            const size_t r = m0 + wm * 64 + im * 16 + grp + half * 8;
            const float2 gr = *reinterpret_cast<const float2*>(gi + r * G3 + ch0);
            const float2 gz = *reinterpret_cast<const float2*>(gi + r * G3 + 256 + ch0);
            const float2 gn = *reinterpret_cast<const float2*>(gi + r * G3 + 512 + ch0);
            const __nv_bfloat16* hp = A + r * (size_t)lda + 3 * ch0;
            const float h0 = __bfloat162float(hp[0]) + __bfloat162float(hp[1]);
            const float h1 = __bfloat162float(hp[3]) + __bfloat162float(hp[4]);

            const int v = half * 2;
            float rr = sigf(gr.x + bi_r0 + acc[im][0][v]     + bh_r0);
            float zz = sigf(gz.x + bi_z0 + acc[im][1][v]     + bh_z0);
            float nn = tanhf(gn.x + bi_n0 + rr * (acc[im][2][v] + bh_n0));
            const float o0 = (1.f - zz) * nn + zz * h0;
            rr = sigf(gr.y + bi_r1 + acc[im][0][v + 1] + bh_r1);
            zz = sigf(gz.y + bi_z1 + acc[im][1][v + 1] + bh_z1);
            nn = tanhf(gn.y + bi_n1 + rr * (acc[im][2][v + 1] + bh_n1));
            const float o1 = (1.f - zz) * nn + zz * h1;

            __nv_bfloat16 ob[6];
            ob[0] = __float2bfloat16_rn(o0);
            ob[1] = __float2bfloat16_rn(o0 - __bfloat162float(ob[0]));
            ob[2] = ob[0];
            ob[3] = __float2bfloat16_rn(o1);
            ob[4] = __float2bfloat16_rn(o1 - __bfloat162float(ob[3]));
            ob[5] = ob[3];
            uint32_t* dst = reinterpret_cast<uint32_t*>(hout + r * (size_t)ho_ld + 3 * ch0);
            const uint32_t* src = reinterpret_cast<const uint32_t*>(ob);
            dst[0] = src[0]; dst[1] = src[1]; dst[2] = src[2];
        }
    }
}

// ---------------------------------------------------------------------------
// Conv1d(k=3,pad=1) + BN partial stats (fp32). Output -> g_gi (aliased).
// ---------------------------------------------------------------------------
__global__ __launch_bounds__(128) void conv_kernel(
    const float* __restrict__ tracks, const float* __restrict__ conv_w)
{
    __shared__ float s_in[32 * CIN * TT];
    const int c  = threadIdx.x;
    const int n0 = blockIdx.x * 32;

    float w[CIN * 3];
    #pragma unroll
    for (int j = 0; j < CIN * 3; j++) w[j] = conv_w[c * (CIN * 3) + j];

    for (int idx = c; idx < 32 * CIN * TT; idx += 128)
        s_in[idx] = tracks[(size_t)n0 * (CIN * TT) + idx];
    __syncthreads();

    float sum = 0.f, sq = 0.f;
    for (int nl = 0; nl < 32; nl++) {
        const float* in = &s_in[nl * CIN * TT];
        #pragma unroll
        for (int t = 0; t < TT; t++) {
            float a = 0.f;
            #pragma unroll
            for (int ci = 0; ci < CIN; ci++) {
                #pragma unroll
                for (int k = 0; k < 3; k++) {
                    const int tt = t + k - 1;
                    if (tt >= 0 && tt < TT)
                        a += in[ci * TT + tt] * w[ci * 3 + k];
                }
            }
            g_gi[((size_t)t * NN + n0 + nl) * COUT + c] = a;
            sum += a; sq += a * a;
        }
    }
    g_part[blockIdx.x * COUT + c] = sum;
    g_part[2048 * COUT + blockIdx.x * COUT + c] = sq;
}

__global__ void bn_finalize_kernel(const float* __restrict__ gamma,
                                   const float* __restrict__ beta)
{
    const int c = threadIdx.x;
    double s = 0.0, q = 0.0;
    for (int b = 0; b < 2048; b++) {
        s += (double)g_part[b * COUT + c];
        q += (double)g_part[2048 * COUT + b * COUT + c];
    }
    const double inv = 1.0 / ((double)TT * (double)NN);
    const double mean = s * inv;
    const double var  = q * inv - mean * mean;
    const float sc = gamma[c] * rsqrtf((float)var + 1e-5f);
    g_bnscale[c] = sc;
    g_bnshift[c] = beta[c] - (float)mean * sc;
}

// BN + ReLU on conv out (in g_gi), expand triplets into g_aug3 cols [0,384)
__global__ __launch_bounds__(256) void bn_relu_expand_kernel()
{
    const size_t i = (size_t)blockIdx.x * 256 + threadIdx.x;
    const int c = (int)(i & (COUT - 1));
    const size_t m = i >> 7;
    float v = g_gi[i] * g_bnscale[c] + g_bnshift[c];
    v = v > 0.f ? v : 0.f;
    const __nv_bfloat16 hi = __float2bfloat16_rn(v);
    const __nv_bfloat16 lo = __float2bfloat16_rn(v - __bfloat162float(hi));
    __nv_bfloat16* o = g_aug3 + m * KA + 3 * c;
    o[0] = hi; o[1] = lo; o[2] = hi;
}

__global__ __launch_bounds__(256) void expand_weight_kernel(
    const float* __restrict__ w, __nv_bfloat16* __restrict__ out, int n)
{
    const int i = blockIdx.x * 256 + threadIdx.x;
    if (i >= n) return;
    const float v = w[i];
    const __nv_bfloat16 hi = __float2bfloat16_rn(v);
    const __nv_bfloat16 lo = __float2bfloat16_rn(v - __bfloat162float(hi));
    out[3 * i + 0] = hi; out[3 * i + 1] = hi; out[3 * i + 2] = lo;
}

// ---------------------------------------------------------------------------
// First-step GRU gates (h_prev = 0, gh = b_hh): elementwise
// ---------------------------------------------------------------------------
__global__ __launch_bounds__(256) void gru_gates_first_kernel(
    const float* __restrict__ gi,
    __nv_bfloat16* __restrict__ hout, size_t ho_ld,
    const float* __restrict__ bih, const float* __restrict__ bhh)
{
    const size_t n = blockIdx.x;
    const int c = threadIdx.x;
    const float* gir = gi + n * G3;
    const float ir  = gir[c]       + bih[c]       + bhh[c];
    const float iz  = gir[c + 256] + bih[c + 256] + bhh[c + 256];
    const float in_ = gir[c + 512] + bih[c + 512];
    const float r = sigf(ir);
    const float z = sigf(iz);
    const float nn2 = tanhf(in_ + r * bhh[c + 512]);
    const float ho = (1.f - z) * nn2;
    const __nv_bfloat16 hi = __float2bfloat16_rn(ho);
    const __nv_bfloat16 lo = __float2bfloat16_rn(ho - __bfloat162float(hi));
    __nv_bfloat16* o = hout + n * ho_ld + 3 * c;
    o[0] = hi; o[1] = lo; o[2] = hi;
}

// ---------------------------------------------------------------------------
// bias + LayerNorm + leaky ReLU in place on d_out
// ---------------------------------------------------------------------------
__global__ __launch_bounds__(256) void ln_leaky_kernel(
    float* __restrict__ y, const float* __restrict__ dec_b,
    const float* __restrict__ ln_w, const float* __restrict__ ln_b)
{
    __shared__ float red[256];
    const size_t r = blockIdx.x;
    const int c = threadIdx.x;
    const float v = y[r * OUTD + c] + dec_b[c];

    red[c] = v;
    __syncthreads();
    #pragma unroll
    for (int s = 128; s > 0; s >>= 1) {
        if (c < s) red[c] += red[c + s];
        __syncthreads();
    }
    const float mean = red[0] * (1.f / OUTD);
    __syncthreads();

    const float d = v - mean;
    red[c] = d * d;
    __syncthreads();
    #pragma unroll
    for (int s = 128; s > 0; s >>= 1) {
        if (c < s) red[c] += red[c + s];
        __syncthreads();
    }
    const float var = red[0] * (1.f / OUTD);

    const float o = d * rsqrtf(var + 1e-5f) * ln_w[c] + ln_b[c];
    y[r * OUTD + c] = o >= 0.f ? o : 0.05f * o;
}

// ---------------------------------------------------------------------------
// Launch
// ---------------------------------------------------------------------------
extern "C" void kernel_launch(void* const* d_in, const int* in_sizes, int n_in,
                              void* d_out, int out_size)
{
    const float* tracks   = (const float*)d_in[0];
    const float* conv_w   = (const float*)d_in[1];
    const float* bn_gamma = (const float*)d_in[2];
    const float* bn_beta  = (const float*)d_in[3];
    const float* g1_wih   = (const float*)d_in[4];
    const float* g1_whh   = (const float*)d_in[5];
    const float* g1_bih   = (const float*)d_in[6];
    const float* g1_bhh   = (const float*)d_in[7];
    const float* g2_wih   = (const float*)d_in[8];
    const float* g2_whh   = (const float*)d_in[9];
    const float* g2_bih   = (const float*)d_in[10];
    const float* g2_bhh   = (const float*)d_in[11];
    const float* dec_w    = (const float*)d_in[12];
    const float* dec_b    = (const float*)d_in[13];
    const float* ln_w     = (const float*)d_in[14];
    const float* ln_b     = (const float*)d_in[15];
    float* out = (float*)d_out;

    __nv_bfloat16 *aug3, *feats3, *w1ih3, *w1hh3, *w2ih3, *w2hh3, *dec3;
    float *gi;
    cudaGetSymbolAddress((void**)&aug3,   g_aug3);
    cudaGetSymbolAddress((void**)&feats3, g_feats3);
    cudaGetSymbolAddress((void**)&gi,     g_gi);
    cudaGetSymbolAddress((void**)&w1ih3,  g_w1ih3);
    cudaGetSymbolAddress((void**)&w1hh3,  g_w1hh3);
    cudaGetSymbolAddress((void**)&w2ih3,  g_w2ih3);
    cudaGetSymbolAddress((void**)&w2hh3,  g_w2hh3);
    cudaGetSymbolAddress((void**)&dec3,   g_dec3);

    cudaFuncSetAttribute(gemm3_kernel,
                         cudaFuncAttributeMaxDynamicSharedMemorySize, GEMM_SMEM);
    cudaFuncSetAttribute(gru_fused_kernel,
                         cudaFuncAttributeMaxDynamicSharedMemorySize, FUSED_SMEM);

    // 0. Expand weights to bf16 triplets
    expand_weight_kernel<<<(G3 * COUT + 255) / 256, 256>>>(g1_wih, w1ih3, G3 * COUT);
    expand_weight_kernel<<<(G3 * HH + 255) / 256, 256>>>(g1_whh, w1hh3, G3 * HH);
    expand_weight_kernel<<<(G3 * (COUT + HH) + 255) / 256, 256>>>(g2_wih, w2ih3, G3 * (COUT + HH));
    expand_weight_kernel<<<(G3 * HH + 255) / 256, 256>>>(g2_whh, w2hh3, G3 * HH);
    expand_weight_kernel<<<(OUTD * TT * HH + 255) / 256, 256>>>(dec_w, dec3, OUTD * TT * HH);

    // 1. Conv (out -> g_gi alias) + BN stats + BN/ReLU/expand into aug3[:,0:384)
    conv_kernel<<<NN / 32, 128>>>(tracks, conv_w);
    bn_finalize_kernel<<<1, 128>>>(bn_gamma, bn_beta);
    bn_relu_expand_kernel<<<((size_t)TT * NN * COUT) / 256, 256>>>();

    const dim3 ggrid(G3 / 128, NN / 128);   // gi GEMM grid (3072 CTAs)
    const dim3 fgrid(HH / 32, NN / 128);    // fused GEMM grid (4096 CTAs)

    // 2+3. GRU1 backward over t
    for (int t = TT - 1; t >= 0; t--) {
        gemm3_kernel<<<ggrid, 256, GEMM_SMEM>>>(
            aug3 + (size_t)t * NN * KA, KA, w1ih3, K1, gi, G3, K1 / 64);
        if (t == TT - 1) {
            gru_gates_first_kernel<<<NN, 256>>>(
                gi, aug3 + (size_t)t * NN * KA + K1, KA, g1_bih, g1_bhh);
        } else {
            gru_fused_kernel<<<fgrid, 256, FUSED_SMEM>>>(
                aug3 + (size_t)(t + 1) * NN * KA + K1, KA, w1hh3, gi,
                aug3 + (size_t)t * NN * KA + K1, KA, g1_bih, g1_bhh);
        }
    }

    // 4+5. GRU2 forward over t; hidden written straight into decoder layout
    for (int t = 0; t < TT; t++) {
        gemm3_kernel<<<ggrid, 256, GEMM_SMEM>>>(
            aug3 + (size_t)t * NN * KA, KA, w2ih3, KA, gi, G3, KA / 64);
        if (t == 0) {
            gru_gates_first_kernel<<<NN, 256>>>(
                gi, feats3, KD, g2_bih, g2_bhh);
        } else {
            gru_fused_kernel<<<fgrid, 256, FUSED_SMEM>>>(
                feats3 + (size_t)(t - 1) * KH, KD, w2hh3, gi,
                feats3 + (size_t)t * KH, KD, g2_bih, g2_bhh);
        }
    }

    // 6. Decoder GEMM into d_out, then fused bias+LN+leaky
    gemm3_kernel<<<dim3(OUTD / 128, NN / 128), 256, GEMM_SMEM>>>(
        feats3, KD, dec3, KD, out, OUTD, KD / 64);
    ln_leaky_kernel<<<NN, 256>>>(out, dec_b, ln_w, ln_b);
}

// round 11
// speedup vs baseline: 2.3815x; 1.0007x over previous
#include <cuda_runtime.h>
#include <cuda_bf16.h>
#include <math.h>
#include <stdint.h>

// ---------------------------------------------------------------------------
// Problem constants
// ---------------------------------------------------------------------------
#define NN 65536
#define CIN 8
#define COUT 128
#define HH 256
#define OUTD 256
#define TT 5
#define G3 768             // 3*H (gate dim)
#define K1 (3*COUT)        // 384   expanded K: x only
#define KH (3*HH)          // 768   expanded K: hidden
#define KA (3*(COUT+HH))   // 1152  expanded K: [x | h1]
#define KD (3*TT*HH)       // 3840  expanded K: decoder input

// ---------------------------------------------------------------------------
// Device scratch — ~1.47 GB (< 2 GiB or GOTPCREL link failure; learned R5)
// ---------------------------------------------------------------------------
__device__ __align__(256) __nv_bfloat16  g_aug3[(size_t)TT * NN * KA];   // 755 MB triplets: x | h1
__device__ __align__(256) __nv_bfloat16  g_feats3[(size_t)NN * KD];      // 503 MB GRU2 states
__device__ __align__(256) float          g_gi[(size_t)NN * G3];          // 201 MB per-step gi (aliases conv out)
__device__ __align__(256) float          g_part[2 * 2048 * COUT];
__device__ float          g_bnscale[COUT];
__device__ float          g_bnshift[COUT];
__device__ __align__(256) __nv_bfloat16  g_w1ih3[G3 * K1];
__device__ __align__(256) __nv_bfloat16  g_w1hh3[G3 * KH];
__device__ __align__(256) __nv_bfloat16  g_w2ih3[G3 * KA];
__device__ __align__(256) __nv_bfloat16  g_w2hh3[G3 * KH];
__device__ __align__(256) __nv_bfloat16  g_dec3[OUTD * KD];

// ---------------------------------------------------------------------------
// Helpers (baseline PTX: cp.async / ldmatrix / mma.sync — target is sm_100)
// ---------------------------------------------------------------------------
__device__ __forceinline__ uint32_t smem_u32(const void* p) {
    uint32_t a;
    asm("{ .reg .u64 t; cvta.to.shared.u64 t, %1; cvt.u32.u64 %0, t; }"
        : "=r"(a) : "l"(p));
    return a;
}
#define SW128(x) ((x) ^ (((x) >> 3) & 0x70))

#define CP_ASYNC16(dst, src) \
    asm volatile("cp.async.cg.shared.global [%0], [%1], 16;" \
        :: "r"(dst), "l"(src) : "memory")
#define CP_COMMIT()  asm volatile("cp.async.commit_group;" ::: "memory")
#define CP_WAIT1()   asm volatile("cp.async.wait_group 1;" ::: "memory")

#define LDMATRIX_X4(r0, r1, r2, r3, addr) \
    asm volatile("ldmatrix.sync.aligned.m8n8.x4.shared.b16 {%0,%1,%2,%3}, [%4];" \
        : "=r"(r0), "=r"(r1), "=r"(r2), "=r"(r3) : "r"(addr))
#define LDMATRIX_X2(r0, r1, addr) \
    asm volatile("ldmatrix.sync.aligned.m8n8.x2.shared.b16 {%0,%1}, [%2];" \
        : "=r"(r0), "=r"(r1) : "r"(addr))

#define MMA_BF16(d, a, b) \
    asm volatile("mma.sync.aligned.m16n8k16.row.col.f32.bf16.bf16.f32 " \
        "{%0,%1,%2,%3}, {%4,%5,%6,%7}, {%8,%9}, {%0,%1,%2,%3};" \
        : "+f"((d)[0]), "+f"((d)[1]), "+f"((d)[2]), "+f"((d)[3]) \
        : "r"((a)[0]), "r"((a)[1]), "r"((a)[2]), "r"((a)[3]), \
          "r"((b)[0]), "r"((b)[1]))

__device__ __forceinline__ float sigf(float x) { return 1.f / (1.f + expf(-x)); }

// ---------------------------------------------------------------------------
// HMMA GEMM:  C[m][n] = sum_k A[m][k]*B[n][k]   (both K-major bf16, C fp32)
// CTA tile 128x128x64, 3-stage cp.async, SW128 + ldmatrix.
// EXACT R8-proven version (B fragments via X2 ldmatrix).
// ---------------------------------------------------------------------------
#define STAGE_BYTES 32768                // A 16KB + B 16KB
#define GEMM_SMEM   (3 * STAGE_BYTES + 1024)

__global__ void __launch_bounds__(256, 2) gemm3_kernel(
    const __nv_bfloat16* __restrict__ A, int lda,
    const __nv_bfloat16* __restrict__ B, int ldb,
    float* __restrict__ C, int ldc, int ktiles)
{
    extern __shared__ char smem_raw[];
    const uint32_t sb = (smem_u32(smem_raw) + 1023u) & ~1023u;

    const int tid  = threadIdx.x;
    const int wid  = tid >> 5;
    const int lane = tid & 31;
    const int wm = wid & 1;
    const int wn = wid >> 1;
    const size_t m0 = (size_t)blockIdx.y * 128;
    const int    n0 = blockIdx.x * 128;

    float acc[4][4][4];
    #pragma unroll
    for (int i = 0; i < 4; i++)
        #pragma unroll
        for (int j = 0; j < 4; j++)
            #pragma unroll
            for (int v = 0; v < 4; v++) acc[i][j][v] = 0.f;

    #pragma unroll
    for (int s = 0; s < 2; s++) {
        const uint32_t sA = sb + s * STAGE_BYTES;
        const uint32_t sB = sA + 16384u;
        #pragma unroll
        for (int i = 0; i < 4; i++) {
            const int idx = tid + (i << 8);
            const int r = idx >> 3, c = idx & 7;
            const __nv_bfloat16* ga = A + (m0 + r) * (size_t)lda + (size_t)s * 64 + c * 8;
            const __nv_bfloat16* gb = B + (size_t)(n0 + r) * (size_t)ldb + (size_t)s * 64 + c * 8;
            CP_ASYNC16(sA + (uint32_t)SW128(r * 128 + c * 16), ga);
            CP_ASYNC16(sB + (uint32_t)SW128(r * 128 + c * 16), gb);
        }
        CP_COMMIT();
    }

    for (int kt = 0; kt < ktiles; kt++) {
        CP_WAIT1();
        __syncthreads();

        const uint32_t sA = sb + (uint32_t)(kt % 3) * STAGE_BYTES;
        const uint32_t sB = sA + 16384u;

        #pragma unroll
        for (int kc = 0; kc < 4; kc++) {
            uint32_t afr[4][4];
            uint32_t bfr[4][2];
            #pragma unroll
            for (int im = 0; im < 4; im++) {
                const int m  = wm * 64 + im * 16 + ((lane >> 3) & 1) * 8 + (lane & 7);
                const int kk = kc * 16 + (lane >> 4) * 8;
                LDMATRIX_X4(afr[im][0], afr[im][1], afr[im][2], afr[im][3],
                            sA + (uint32_t)SW128(m * 128 + kk * 2));
            }
            #pragma unroll
            for (int in_ = 0; in_ < 4; in_++) {
                const int n  = wn * 32 + in_ * 8 + (lane & 7);
                const int kk = kc * 16 + ((lane >> 3) & 1) * 8;
                LDMATRIX_X2(bfr[in_][0], bfr[in_][1],
                            sB + (uint32_t)SW128(n * 128 + kk * 2));
            }
            #pragma unroll
            for (int im = 0; im < 4; im++)
                #pragma unroll
                for (int in_ = 0; in_ < 4; in_++)
                    MMA_BF16(acc[im][in_], afr[im], bfr[in_]);
        }

        if (kt + 2 < ktiles) {
            const int s = kt + 2;
            const uint32_t dA = sb + (uint32_t)(s % 3) * STAGE_BYTES;
            const uint32_t dB = dA + 16384u;
            #pragma unroll
            for (int i = 0; i < 4; i++) {
                const int idx = tid + (i << 8);
                const int r = idx >> 3, c = idx & 7;
                const __nv_bfloat16* ga = A + (m0 + r) * (size_t)lda + (size_t)s * 64 + c * 8;
                const __nv_bfloat16* gb = B + (size_t)(n0 + r) * (size_t)ldb + (size_t)s * 64 + c * 8;
                CP_ASYNC16(dA + (uint32_t)SW128(r * 128 + c * 16), ga);
                CP_ASYNC16(dB + (uint32_t)SW128(r * 128 + c * 16), gb);
            }
        }
        CP_COMMIT();
    }

    const int grp = lane >> 2;
    const int tig = lane & 3;
    #pragma unroll
    for (int im = 0; im < 4; im++) {
        const size_t row = m0 + wm * 64 + im * 16 + grp;
        #pragma unroll
        for (int in_ = 0; in_ < 4; in_++) {
            const int col = n0 + wn * 32 + in_ * 8 + 2 * tig;
            *reinterpret_cast<float2*>(C + row * (size_t)ldc + col) =
                make_float2(acc[im][in_][0], acc[im][in_][1]);
            *reinterpret_cast<float2*>(C + (row + 8) * (size_t)ldc + col) =
                make_float2(acc[im][in_][2], acc[im][in_][3]);
        }
    }
}

// ---------------------------------------------------------------------------
// Fused hidden-GEMM + GRU gates.
// gh = h_prev @ Whh^T for a 128x96 tile; 96 cols = 4 N-warps x (3 gates x
// 8 channels), B rows gate-strided from Whh so each thread holds r/z/n of the
// same channel. Epilogue does exact fp32 gate math and writes h_t triplets.
// A tile = 128 rows x 128B = 1024 16B-chunks = 4/thread (R9 bug: was 8/thread
// -> OOB global reads at rows m0+128..m0+255).
// K = KH = 768 fixed (12 k-tiles). Grid: (HH/32 = 8, M/128).
// ---------------------------------------------------------------------------
#define FSTAGE_BYTES (16384 + 12288)     // A 16KB + B 12KB (96 rows x 128B)
#define FUSED_SMEM   (3 * FSTAGE_BYTES + 1024)

__global__ void __launch_bounds__(256, 2) gru_fused_kernel(
    const __nv_bfloat16* __restrict__ A, int lda,      // h_prev triplets
    const __nv_bfloat16* __restrict__ Bw,              // whh3 [768][KH]
    const float* __restrict__ gi,                      // [M][768]
    __nv_bfloat16* __restrict__ hout, int ho_ld,
    const float* __restrict__ bih, const float* __restrict__ bhh)
{
    extern __shared__ char smem_raw[];
    const uint32_t sb = (smem_u32(smem_raw) + 1023u) & ~1023u;

    const int tid  = threadIdx.x;
    const int wid  = tid >> 5;
    const int lane = tid & 31;
    const int wm = wid & 1;              // 2 M-warps (64 rows)
    const int wn = wid >> 1;             // 4 N-warps (24 cols: 3 gates x 8 ch)
    const size_t m0 = (size_t)blockIdx.y * 128;
    const int chblk = blockIdx.x;        // 32 channels per block

    const int KT = KH / 64;              // 12

    float acc[4][3][4];
    #pragma unroll
    for (int i = 0; i < 4; i++)
        #pragma unroll
        for (int g = 0; g < 3; g++)
            #pragma unroll
            for (int v = 0; v < 4; v++) acc[i][g][v] = 0.f;

    // loaders: A 1024 chunks (4/thread), B 768 chunks (3/thread)
    #pragma unroll
    for (int s = 0; s < 2; s++) {
        const uint32_t sA = sb + s * FSTAGE_BYTES;
        const uint32_t sB = sA + 16384u;
        #pragma unroll
        for (int i = 0; i < 4; i++) {
            const int idx = tid + (i << 8);
            const int r = idx >> 3, c = idx & 7;
            const __nv_bfloat16* ga = A + (m0 + r) * (size_t)lda + (size_t)s * 64 + c * 8;
            CP_ASYNC16(sA + (uint32_t)SW128(r * 128 + c * 16), ga);
        }
        #pragma unroll
        for (int i = 0; i < 3; i++) {
            const int idx = tid + (i << 8);
            const int j = idx >> 3, c = idx & 7;
            const int jw = j / 24, rem = j % 24;
            const int grow = (rem / 8) * 256 + chblk * 32 + jw * 8 + (rem & 7);
            const __nv_bfloat16* gb = Bw + (size_t)grow * KH + (size_t)s * 64 + c * 8;
            CP_ASYNC16(sB + (uint32_t)SW128(j * 128 + c * 16), gb);
        }
        CP_COMMIT();
    }

    for (int kt = 0; kt < KT; kt++) {
        CP_WAIT1();
        __syncthreads();

        const uint32_t sA = sb + (uint32_t)(kt % 3) * FSTAGE_BYTES;
        const uint32_t sB = sA + 16384u;

        #pragma unroll
        for (int kc = 0; kc < 4; kc++) {
            uint32_t afr[4][4];
            uint32_t bfr[3][2];
            #pragma unroll
            for (int im = 0; im < 4; im++) {
                const int m  = wm * 64 + im * 16 + ((lane >> 3) & 1) * 8 + (lane & 7);
                const int kk = kc * 16 + (lane >> 4) * 8;
                LDMATRIX_X4(afr[im][0], afr[im][1], afr[im][2], afr[im][3],
                            sA + (uint32_t)SW128(m * 128 + kk * 2));
            }
            #pragma unroll
            for (int g = 0; g < 3; g++) {
                const int j  = wn * 24 + g * 8 + (lane & 7);
                const int kk = kc * 16 + ((lane >> 3) & 1) * 8;
                LDMATRIX_X2(bfr[g][0], bfr[g][1],
                            sB + (uint32_t)SW128(j * 128 + kk * 2));
            }
            #pragma unroll
            for (int im = 0; im < 4; im++)
                #pragma unroll
                for (int g = 0; g < 3; g++)
                    MMA_BF16(acc[im][g], afr[im], bfr[g]);
        }

        if (kt + 2 < KT) {
            const int s = kt + 2;
            const uint32_t dA = sb + (uint32_t)(s % 3) * FSTAGE_BYTES;
            const uint32_t dB = dA + 16384u;
            #pragma unroll
            for (int i = 0; i < 4; i++) {
                const int idx = tid + (i << 8);
                const int r = idx >> 3, c = idx & 7;
                const __nv_bfloat16* ga = A + (m0 + r) * (size_t)lda + (size_t)s * 64 + c * 8;
                CP_ASYNC16(dA + (uint32_t)SW128(r * 128 + c * 16), ga);
            }
            #pragma unroll
            for (int i = 0; i < 3; i++) {
                const int idx = tid + (i << 8);
                const int j = idx >> 3, c = idx & 7;
                const int jw = j / 24, rem = j % 24;
                const int grow = (rem / 8) * 256 + chblk * 32 + jw * 8 + (rem & 7);
                const __nv_bfloat16* gb = Bw + (size_t)grow * KH + (size_t)s * 64 + c * 8;
                CP_ASYNC16(dB + (uint32_t)SW128(j * 128 + c * 16), gb);
            }
        }
        CP_COMMIT();
    }

    // ---- fused gate epilogue ----
    const int grp = lane >> 2;
    const int tig = lane & 3;
    const int ch0 = chblk * 32 + wn * 8 + 2 * tig;    // channel pair base
    const float bi_r0 = bih[ch0],       bi_r1 = bih[ch0 + 1];
    const float bi_z0 = bih[256 + ch0], bi_z1 = bih[256 + ch0 + 1];
    const float bi_n0 = bih[512 + ch0], bi_n1 = bih[512 + ch0 + 1];
    const float bh_r0 = bhh[ch0],       bh_r1 = bhh[ch0 + 1];
    const float bh_z0 = bhh[256 + ch0], bh_z1 = bhh[256 + ch0 + 1];
    const float bh_n0 = bhh[512 + ch0], bh_n1 = bhh[512 + ch0 + 1];

    #pragma unroll
    for (int im = 0; im < 4; im++) {
        #pragma unroll
        for (int half = 0; half < 2; half++) {
            const size_t r = m0 + wm * 64 + im * 16 + grp + half * 8;
            const float2 gr = *reinterpret_cast<const float2*>(gi + r * G3 + ch0);
            const float2 gz = *reinterpret_cast<const float2*>(gi + r * G3 + 256 + ch0);
            const float2 gn = *reinterpret_cast<const float2*>(gi + r * G3 + 512 + ch0);
            const __nv_bfloat16* hp = A + r * (size_t)lda + 3 * ch0;
            const float h0 = __bfloat162float(hp[0]) + __bfloat162float(hp[1]);
            const float h1 = __bfloat162float(hp[3]) + __bfloat162float(hp[4]);

            const int v = half * 2;
            float rr = sigf(gr.x + bi_r0 + acc[im][0][v]     + bh_r0);
            float zz = sigf(gz.x + bi_z0 + acc[im][1][v]     + bh_z0);
            float nn = tanhf(gn.x + bi_n0 + rr * (acc[im][2][v] + bh_n0));
            const float o0 = (1.f - zz) * nn + zz * h0;
            rr = sigf(gr.y + bi_r1 + acc[im][0][v + 1] + bh_r1);
            zz = sigf(gz.y + bi_z1 + acc[im][1][v + 1] + bh_z1);
            nn = tanhf(gn.y + bi_n1 + rr * (acc[im][2][v + 1] + bh_n1));
            const float o1 = (1.f - zz) * nn + zz * h1;

            __nv_bfloat16 ob[6];
            ob[0] = __float2bfloat16_rn(o0);
            ob[1] = __float2bfloat16_rn(o0 - __bfloat162float(ob[0]));
            ob[2] = ob[0];
            ob[3] = __float2bfloat16_rn(o1);
            ob[4] = __float2bfloat16_rn(o1 - __bfloat162float(ob[3]));
            ob[5] = ob[3];
            uint32_t* dst = reinterpret_cast<uint32_t*>(hout + r * (size_t)ho_ld + 3 * ch0);
            const uint32_t* src = reinterpret_cast<const uint32_t*>(ob);
            dst[0] = src[0]; dst[1] = src[1]; dst[2] = src[2];
        }
    }
}

// ---------------------------------------------------------------------------
// Conv1d(k=3,pad=1) + BN partial stats (fp32). Output -> g_gi (aliased).
// ---------------------------------------------------------------------------
__global__ __launch_bounds__(128) void conv_kernel(
    const float* __restrict__ tracks, const float* __restrict__ conv_w)
{
    __shared__ float s_in[32 * CIN * TT];
    const int c  = threadIdx.x;
    const int n0 = blockIdx.x * 32;

    float w[CIN * 3];
    #pragma unroll
    for (int j = 0; j < CIN * 3; j++) w[j] = conv_w[c * (CIN * 3) + j];

    for (int idx = c; idx < 32 * CIN * TT; idx += 128)
        s_in[idx] = tracks[(size_t)n0 * (CIN * TT) + idx];
    __syncthreads();

    float sum = 0.f, sq = 0.f;
    for (int nl = 0; nl < 32; nl++) {
        const float* in = &s_in[nl * CIN * TT];
        #pragma unroll
        for (int t = 0; t < TT; t++) {
            float a = 0.f;
            #pragma unroll
            for (int ci = 0; ci < CIN; ci++) {
                #pragma unroll
                for (int k = 0; k < 3; k++) {
                    const int tt = t + k - 1;
                    if (tt >= 0 && tt < TT)
                        a += in[ci * TT + tt] * w[ci * 3 + k];
                }
            }
            g_gi[((size_t)t * NN + n0 + nl) * COUT + c] = a;
            sum += a; sq += a * a;
        }
    }
    g_part[blockIdx.x * COUT + c] = sum;
    g_part[2048 * COUT + blockIdx.x * COUT + c] = sq;
}

__global__ void bn_finalize_kernel(const float* __restrict__ gamma,
                                   const float* __restrict__ beta)
{
    const int c = threadIdx.x;
    double s = 0.0, q = 0.0;
    for (int b = 0; b < 2048; b++) {
        s += (double)g_part[b * COUT + c];
        q += (double)g_part[2048 * COUT + b * COUT + c];
    }
    const double inv = 1.0 / ((double)TT * (double)NN);
    const double mean = s * inv;
    const double var  = q * inv - mean * mean;
    const float sc = gamma[c] * rsqrtf((float)var + 1e-5f);
    g_bnscale[c] = sc;
    g_bnshift[c] = beta[c] - (float)mean * sc;
}

// BN + ReLU on conv out (in g_gi), expand triplets into g_aug3 cols [0,384)
__global__ __launch_bounds__(256) void bn_relu_expand_kernel()
{
    const size_t i = (size_t)blockIdx.x * 256 + threadIdx.x;
    const int c = (int)(i & (COUT - 1));
    const size_t m = i >> 7;
    float v = g_gi[i] * g_bnscale[c] + g_bnshift[c];
    v = v > 0.f ? v : 0.f;
    const __nv_bfloat16 hi = __float2bfloat16_rn(v);
    const __nv_bfloat16 lo = __float2bfloat16_rn(v - __bfloat162float(hi));
    __nv_bfloat16* o = g_aug3 + m * KA + 3 * c;
    o[0] = hi; o[1] = lo; o[2] = hi;
}

__global__ __launch_bounds__(256) void expand_weight_kernel(
    const float* __restrict__ w, __nv_bfloat16* __restrict__ out, int n)
{
    const int i = blockIdx.x * 256 + threadIdx.x;
    if (i >= n) return;
    const float v = w[i];
    const __nv_bfloat16 hi = __float2bfloat16_rn(v);
    const __nv_bfloat16 lo = __float2bfloat16_rn(v - __bfloat162float(hi));
    out[3 * i + 0] = hi; out[3 * i + 1] = hi; out[3 * i + 2] = lo;
}

// ---------------------------------------------------------------------------
// First-step GRU gates (h_prev = 0, gh = b_hh): elementwise
// ---------------------------------------------------------------------------
__global__ __launch_bounds__(256) void gru_gates_first_kernel(
    const float* __restrict__ gi,
    __nv_bfloat16* __restrict__ hout, size_t ho_ld,
    const float* __restrict__ bih, const float* __restrict__ bhh)
{
    const size_t n = blockIdx.x;
    const int c = threadIdx.x;
    const float* gir = gi + n * G3;
    const float ir  = gir[c]       + bih[c]       + bhh[c];
    const float iz  = gir[c + 256] + bih[c + 256] + bhh[c + 256];
    const float in_ = gir[c + 512] + bih[c + 512];
    const float r = sigf(ir);
    const float z = sigf(iz);
    const float nn2 = tanhf(in_ + r * bhh[c + 512]);
    const float ho = (1.f - z) * nn2;
    const __nv_bfloat16 hi = __float2bfloat16_rn(ho);
    const __nv_bfloat16 lo = __float2bfloat16_rn(ho - __bfloat162float(hi));
    __nv_bfloat16* o = hout + n * ho_ld + 3 * c;
    o[0] = hi; o[1] = lo; o[2] = hi;
}

// ---------------------------------------------------------------------------
// bias + LayerNorm + leaky ReLU in place on d_out
// ---------------------------------------------------------------------------
__global__ __launch_bounds__(256) void ln_leaky_kernel(
    float* __restrict__ y, const float* __restrict__ dec_b,
    const float* __restrict__ ln_w, const float* __restrict__ ln_b)
{
    __shared__ float red[256];
    const size_t r = blockIdx.x;
    const int c = threadIdx.x;
    const float v = y[r * OUTD + c] + dec_b[c];

    red[c] = v;
    __syncthreads();
    #pragma unroll
    for (int s = 128; s > 0; s >>= 1) {
        if (c < s) red[c] += red[c + s];
        __syncthreads();
    }
    const float mean = red[0] * (1.f / OUTD);
    __syncthreads();

    const float d = v - mean;
    red[c] = d * d;
    __syncthreads();
    #pragma unroll
    for (int s = 128; s > 0; s >>= 1) {
        if (c < s) red[c] += red[c + s];
        __syncthreads();
    }
    const float var = red[0] * (1.f / OUTD);

    const float o = d * rsqrtf(var + 1e-5f) * ln_w[c] + ln_b[c];
    y[r * OUTD + c] = o >= 0.f ? o : 0.05f * o;
}

// ---------------------------------------------------------------------------
// Launch
// ---------------------------------------------------------------------------
extern "C" void kernel_launch(void* const* d_in, const int* in_sizes, int n_in,
                              void* d_out, int out_size)
{
    const float* tracks   = (const float*)d_in[0];
    const float* conv_w   = (const float*)d_in[1];
    const float* bn_gamma = (const float*)d_in[2];
    const float* bn_beta  = (const float*)d_in[3];
    const float* g1_wih   = (const float*)d_in[4];
    const float* g1_whh   = (const float*)d_in[5];
    const float* g1_bih   = (const float*)d_in[6];
    const float* g1_bhh   = (const float*)d_in[7];
    const float* g2_wih   = (const float*)d_in[8];
    const float* g2_whh   = (const float*)d_in[9];
    const float* g2_bih   = (const float*)d_in[10];
    const float* g2_bhh   = (const float*)d_in[11];
    const float* dec_w    = (const float*)d_in[12];
    const float* dec_b    = (const float*)d_in[13];
    const float* ln_w     = (const float*)d_in[14];
    const float* ln_b     = (const float*)d_in[15];
    float* out = (float*)d_out;

    __nv_bfloat16 *aug3, *feats3, *w1ih3, *w1hh3, *w2ih3, *w2hh3, *dec3;
    float *gi;
    cudaGetSymbolAddress((void**)&aug3,   g_aug3);
    cudaGetSymbolAddress((void**)&feats3, g_feats3);
    cudaGetSymbolAddress((void**)&gi,     g_gi);
    cudaGetSymbolAddress((void**)&w1ih3,  g_w1ih3);
    cudaGetSymbolAddress((void**)&w1hh3,  g_w1hh3);
    cudaGetSymbolAddress((void**)&w2ih3,  g_w2ih3);
    cudaGetSymbolAddress((void**)&w2hh3,  g_w2hh3);
    cudaGetSymbolAddress((void**)&dec3,   g_dec3);

    cudaFuncSetAttribute(gemm3_kernel,
                         cudaFuncAttributeMaxDynamicSharedMemorySize, GEMM_SMEM);
    cudaFuncSetAttribute(gru_fused_kernel,
                         cudaFuncAttributeMaxDynamicSharedMemorySize, FUSED_SMEM);

    // 0. Expand weights to bf16 triplets
    expand_weight_kernel<<<(G3 * COUT + 255) / 256, 256>>>(g1_wih, w1ih3, G3 * COUT);
    expand_weight_kernel<<<(G3 * HH + 255) / 256, 256>>>(g1_whh, w1hh3, G3 * HH);
    expand_weight_kernel<<<(G3 * (COUT + HH) + 255) / 256, 256>>>(g2_wih, w2ih3, G3 * (COUT + HH));
    expand_weight_kernel<<<(G3 * HH + 255) / 256, 256>>>(g2_whh, w2hh3, G3 * HH);
    expand_weight_kernel<<<(OUTD * TT * HH + 255) / 256, 256>>>(dec_w, dec3, OUTD * TT * HH);

    // 1. Conv (out -> g_gi alias) + BN stats + BN/ReLU/expand into aug3[:,0:384)
    conv_kernel<<<NN / 32, 128>>>(tracks, conv_w);
    bn_finalize_kernel<<<1, 128>>>(bn_gamma, bn_beta);
    bn_relu_expand_kernel<<<((size_t)TT * NN * COUT) / 256, 256>>>();

    const dim3 ggrid(G3 / 128, NN / 128);   // gi GEMM grid (3072 CTAs)
    const dim3 fgrid(HH / 32, NN / 128);    // fused GEMM grid (4096 CTAs)

    // 2+3. GRU1 backward over t
    for (int t = TT - 1; t >= 0; t--) {
        gemm3_kernel<<<ggrid, 256, GEMM_SMEM>>>(
            aug3 + (size_t)t * NN * KA, KA, w1ih3, K1, gi, G3, K1 / 64);
        if (t == TT - 1) {
            gru_gates_first_kernel<<<NN, 256>>>(
                gi, aug3 + (size_t)t * NN * KA + K1, KA, g1_bih, g1_bhh);
        } else {
            gru_fused_kernel<<<fgrid, 256, FUSED_SMEM>>>(
                aug3 + (size_t)(t + 1) * NN * KA + K1, KA, w1hh3, gi,
                aug3 + (size_t)t * NN * KA + K1, KA, g1_bih, g1_bhh);
        }
    }

    // 4+5. GRU2 forward over t; hidden written straight into decoder layout
    for (int t = 0; t < TT; t++) {
        gemm3_kernel<<<ggrid, 256, GEMM_SMEM>>>(
            aug3 + (size_t)t * NN * KA, KA, w2ih3, KA, gi, G3, KA / 64);
        if (t == 0) {
            gru_gates_first_kernel<<<NN, 256>>>(
                gi, feats3, KD, g2_bih, g2_bhh);
        } else {
            gru_fused_kernel<<<fgrid, 256, FUSED_SMEM>>>(
                feats3 + (size_t)(t - 1) * KH, KD, w2hh3, gi,
                feats3 + (size_t)t * KH, KD, g2_bih, g2_bhh);
        }
    }

    // 6. Decoder GEMM into d_out, then fused bias+LN+leaky
    gemm3_kernel<<<dim3(OUTD / 128, NN / 128), 256, GEMM_SMEM>>>(
        feats3, KD, dec3, KD, out, OUTD, KD / 64);
    ln_leaky_kernel<<<NN, 256>>>(out, dec_b, ln_w, ln_b);
}